// round 2
// baseline (speedup 1.0000x reference)
#include <cuda_runtime.h>
#include <cstdint>
#include <math.h>

#define B_   64
#define L_   1024
#define IN_  512
#define H_   512
#define G3_  1536
#define NBLK 128

// Scratch (device globals; allocation APIs are forbidden)
__device__ float g_gx[(size_t)2 * L_ * G3_ * B_];   // [d][t][g][b]  ~805 MB
__device__ float g_hbuf[2 * 2 * H_ * B_];           // [d][buf][k][b]
__device__ unsigned g_cnt = 0;
__device__ unsigned g_gen = 0;

// ---------------------------------------------------------------------------
// Kernel 1: input projection  gx[d][t][g][b] = sum_i feats[b, te, i] * w_ih[d][g,i] + b_ih[d][g]
// Tiled SGEMM: 128(g) x 128(tb) x 16 per block, 8x8 per thread, 256 threads.
// ---------------------------------------------------------------------------
__global__ __launch_bounds__(256) void proj_kernel(
    const float* __restrict__ feats,
    const float* __restrict__ w_ih_lr, const float* __restrict__ b_ih_lr,
    const float* __restrict__ w_ih_rl, const float* __restrict__ b_ih_rl)
{
    __shared__ float As[16][136];
    __shared__ float Bs[16][136];

    const int d      = blockIdx.z;
    const int gtile  = blockIdx.x * 128;
    const int tbtile = blockIdx.y * 128;
    const float* W  = d ? w_ih_rl : w_ih_lr;
    const float* bi = d ? b_ih_rl : b_ih_lr;

    const int tid = threadIdx.x;
    const int lr  = tid >> 1;           // 0..127 (row for A, col for B)
    const int lkq = (tid & 1) * 8;      // 0 or 8
    const int ty  = tid >> 4, tx = tid & 15;
    const int m0  = ty * 8,  n0 = tx * 8;

    float acc[8][8];
    #pragma unroll
    for (int i = 0; i < 8; ++i)
        #pragma unroll
        for (int j = 0; j < 8; ++j) acc[i][j] = 0.f;

    // loader source pointers
    const int gtb_l = tbtile + lr;
    const int t_l   = gtb_l >> 6;
    const int b_l   = gtb_l & 63;
    const int te_l  = d ? (1023 - t_l) : t_l;
    const float* bsrc = feats + ((size_t)b_l * L_ + te_l) * IN_;
    const float* asrc = W + (size_t)(gtile + lr) * IN_;

    for (int k0 = 0; k0 < IN_; k0 += 16) {
        float4 a0 = *(const float4*)(asrc + k0 + lkq);
        float4 a1 = *(const float4*)(asrc + k0 + lkq + 4);
        float4 v0 = *(const float4*)(bsrc + k0 + lkq);
        float4 v1 = *(const float4*)(bsrc + k0 + lkq + 4);
        __syncthreads();   // previous tile's compute done
        As[lkq+0][lr] = a0.x; As[lkq+1][lr] = a0.y; As[lkq+2][lr] = a0.z; As[lkq+3][lr] = a0.w;
        As[lkq+4][lr] = a1.x; As[lkq+5][lr] = a1.y; As[lkq+6][lr] = a1.z; As[lkq+7][lr] = a1.w;
        Bs[lkq+0][lr] = v0.x; Bs[lkq+1][lr] = v0.y; Bs[lkq+2][lr] = v0.z; Bs[lkq+3][lr] = v0.w;
        Bs[lkq+4][lr] = v1.x; Bs[lkq+5][lr] = v1.y; Bs[lkq+6][lr] = v1.z; Bs[lkq+7][lr] = v1.w;
        __syncthreads();
        #pragma unroll
        for (int kk = 0; kk < 16; ++kk) {
            float a[8], bb[8];
            *(float4*)&a[0]  = *(const float4*)&As[kk][m0];
            *(float4*)&a[4]  = *(const float4*)&As[kk][m0 + 4];
            *(float4*)&bb[0] = *(const float4*)&Bs[kk][n0];
            *(float4*)&bb[4] = *(const float4*)&Bs[kk][n0 + 4];
            #pragma unroll
            for (int i = 0; i < 8; ++i)
                #pragma unroll
                for (int j = 0; j < 8; ++j)
                    acc[i][j] += a[i] * bb[j];
        }
    }

    // epilogue: add bias, store gx[d][t][g][b]
    const int t_c = (tbtile + n0) >> 6;   // constant across the 8 cols of this thread
    const int b_c = (tbtile + n0) & 63;
    #pragma unroll
    for (int i = 0; i < 8; ++i) {
        const int cg = gtile + m0 + i;
        const float bias = bi[cg];
        float4 o0, o1;
        o0.x = acc[i][0] + bias; o0.y = acc[i][1] + bias;
        o0.z = acc[i][2] + bias; o0.w = acc[i][3] + bias;
        o1.x = acc[i][4] + bias; o1.y = acc[i][5] + bias;
        o1.z = acc[i][6] + bias; o1.w = acc[i][7] + bias;
        const size_t off = (((size_t)d * L_ + t_c) * G3_ + cg) * B_ + b_c;
        *(float4*)&g_gx[off]     = o0;
        *(float4*)&g_gx[off + 4] = o1;
    }
}

// ---------------------------------------------------------------------------
// Grid barrier across all NBLK blocks (self-resetting, graph-replay safe).
// All 128 blocks are wave-1 co-resident (1 block/SM via smem, 128 <= 148 SMs).
// ---------------------------------------------------------------------------
__device__ __forceinline__ void grid_bar()
{
    __syncthreads();
    if (threadIdx.x == 0) {
        __threadfence();
        volatile unsigned* vgen = &g_gen;
        const unsigned snap = *vgen;
        const unsigned old  = atomicAdd(&g_cnt, 1);
        if (old == NBLK - 1) {
            g_cnt = 0;
            __threadfence();
            atomicAdd(&g_gen, 1);
        } else {
            while (*vgen == snap) { __nanosleep(64); }
        }
        __threadfence();
    }
    __syncthreads();
}

// ---------------------------------------------------------------------------
// Kernel 2: persistent recurrence. Grid (64, 2) = (hidden-col slice, direction),
// 512 threads. Block owns 8 hidden columns for all 64 batch rows.
// smem: hs[512][64] staged h, ws[3][8][512] weights, red (k-split partials), hout.
// ---------------------------------------------------------------------------
__global__ void __launch_bounds__(512, 1) gru_kernel(
    const float* __restrict__ mask,
    const float* __restrict__ w_hh_lr, const float* __restrict__ b_hh_lr,
    const float* __restrict__ w_hh_rl, const float* __restrict__ b_hh_rl,
    float* __restrict__ out)
{
    extern __shared__ float sm[];
    float* hs   = sm;            // 32768 floats: hs[k*64 + b]
    float* ws   = sm + 32768;    // 12288 floats: ws[(gate*8+g)*512 + k]
    float* red  = sm + 45056;    // 1536  floats: red[(g*64+b)*3 + {r,z,n}]
    float* hout = sm + 46592;    // 512   floats: hout[b*8 + g]

    const int d  = blockIdx.y;
    const int c0 = blockIdx.x * 8;
    const float* whh = d ? w_hh_rl : w_hh_lr;
    const float* bhh = d ? b_hh_rl : b_hh_lr;

    const int tid = threadIdx.x;
    const int bh  = tid & 31;          // batch lane (handles bh and bh+32)
    const int gi  = (tid >> 5) & 7;    // which of 8 hidden columns
    const int kh  = tid >> 8;          // k-split half (0 or 1)

    // load weight slice into smem
    for (int i = tid; i < 3072; i += 512) {
        const int fi   = i << 2;
        const int row  = fi >> 9;          // gate*8+g
        const int k    = fi & 511;
        const int gate = row >> 3, g = row & 7;
        *(float4*)&ws[fi] =
            *(const float4*)&whh[((size_t)(gate * H_ + c0 + g)) * H_ + k];
    }
    // zero our slice of h buffer 0
    {
        const int gg = tid >> 6, b = tid & 63;
        g_hbuf[((d * 2 + 0) * H_ + c0 + gg) * B_ + b] = 0.f;
    }
    grid_bar();

    const float* wr = &ws[(0 * 8 + gi) * 512];
    const float* wz = &ws[(1 * 8 + gi) * 512];
    const float* wn = &ws[(2 * 8 + gi) * 512];
    const int k0 = kh << 8;

    for (int t = 0; t < L_; ++t) {
        const int cur = t & 1, nxt = cur ^ 1;

        // stage full h[512][64] into smem (coalesced float4)
        const float4* hsrc = (const float4*)&g_hbuf[(d * 2 + cur) * H_ * B_];
        float4* hdst = (float4*)hs;
        #pragma unroll
        for (int i = 0; i < 16; ++i)
            hdst[tid + i * 512] = hsrc[tid + i * 512];
        __syncthreads();

        // partial dot products over our k-half
        float ar0 = 0.f, az0 = 0.f, an0 = 0.f;
        float ar1 = 0.f, az1 = 0.f, an1 = 0.f;
        #pragma unroll 8
        for (int k = k0; k < k0 + 256; k += 4) {
            const float4 wrv = *(const float4*)&wr[k];
            const float4 wzv = *(const float4*)&wz[k];
            const float4 wnv = *(const float4*)&wn[k];
            const float* hp = &hs[k * 64 + bh];
            float ha, hb;
            ha = hp[0];   hb = hp[32];
            ar0 += wrv.x * ha; az0 += wzv.x * ha; an0 += wnv.x * ha;
            ar1 += wrv.x * hb; az1 += wzv.x * hb; an1 += wnv.x * hb;
            ha = hp[64];  hb = hp[96];
            ar0 += wrv.y * ha; az0 += wzv.y * ha; an0 += wnv.y * ha;
            ar1 += wrv.y * hb; az1 += wzv.y * hb; an1 += wnv.y * hb;
            ha = hp[128]; hb = hp[160];
            ar0 += wrv.z * ha; az0 += wzv.z * ha; an0 += wnv.z * ha;
            ar1 += wrv.z * hb; az1 += wzv.z * hb; an1 += wnv.z * hb;
            ha = hp[192]; hb = hp[224];
            ar0 += wrv.w * ha; az0 += wzv.w * ha; an0 += wnv.w * ha;
            ar1 += wrv.w * hb; az1 += wzv.w * hb; an1 += wnv.w * hb;
        }

        if (kh) {
            float* r0 = &red[(gi * 64 + bh) * 3];
            r0[0] = ar0; r0[1] = az0; r0[2] = an0;
            float* r1 = &red[(gi * 64 + bh + 32) * 3];
            r1[0] = ar1; r1[1] = az1; r1[2] = an1;
        }
        __syncthreads();

        if (!kh) {
            const int te = d ? (1023 - t) : t;
            const size_t gxbase = (((size_t)d * L_ + t) * G3_) * B_;
            const int cg = c0 + gi;
            const float br = bhh[cg], bz = bhh[H_ + cg], bn = bhh[2 * H_ + cg];
            #pragma unroll
            for (int p = 0; p < 2; ++p) {
                const int b = bh + p * 32;
                const float* rr = &red[(gi * 64 + b) * 3];
                const float hr = (p ? ar1 : ar0) + rr[0] + br;
                const float hz = (p ? az1 : az0) + rr[1] + bz;
                const float hn = (p ? an1 : an0) + rr[2] + bn;
                const float xr = g_gx[gxbase + (size_t)cg * B_ + b];
                const float xz = g_gx[gxbase + (size_t)(H_ + cg) * B_ + b];
                const float xn = g_gx[gxbase + (size_t)(2 * H_ + cg) * B_ + b];
                const float r = 1.f / (1.f + expf(-(xr + hr)));
                const float z = 1.f / (1.f + expf(-(xz + hz)));
                const float n = tanhf(xn + r * hn);
                const float hprev = hs[cg * 64 + b];
                const float hnew  = (1.f - z) * n + z * hprev;
                const float mk = mask[(size_t)b * L_ + te];
                const float h  = mk * hnew + (1.f - mk) * hprev;
                g_hbuf[((d * 2 + nxt) * H_ + cg) * B_ + b] = h;
                hout[b * 8 + gi] = h;
            }
        }
        __syncthreads();

        // coalesced-ish output write: 32B contiguous per (b, block)
        if (tid < 64) {
            const int b = tid;
            const int l = d ? (1023 - t) : t;
            float4* dst = (float4*)&out[((size_t)b * L_ + l) * 1024 + d * H_ + c0];
            dst[0] = *(float4*)&hout[b * 8];
            dst[1] = *(float4*)&hout[b * 8 + 4];
        }
        grid_bar();
    }
}

// ---------------------------------------------------------------------------
extern "C" void kernel_launch(void* const* d_in, const int* in_sizes, int n_in,
                              void* d_out, int out_size)
{
    const float* feats   = (const float*)d_in[0];
    const float* mask    = (const float*)d_in[1];
    const float* w_ih_lr = (const float*)d_in[2];
    const float* w_hh_lr = (const float*)d_in[3];
    const float* b_ih_lr = (const float*)d_in[4];
    const float* b_hh_lr = (const float*)d_in[5];
    const float* w_ih_rl = (const float*)d_in[6];
    const float* w_hh_rl = (const float*)d_in[7];
    const float* b_ih_rl = (const float*)d_in[8];
    const float* b_hh_rl = (const float*)d_in[9];
    float* out = (float*)d_out;

    const int smem_gru = (32768 + 12288 + 1536 + 512) * 4;  // 188416 B
    cudaFuncSetAttribute(gru_kernel, cudaFuncAttributeMaxDynamicSharedMemorySize, smem_gru);

    proj_kernel<<<dim3(12, 512, 2), 256>>>(feats, w_ih_lr, b_ih_lr, w_ih_rl, b_ih_rl);
    gru_kernel<<<dim3(64, 2), 512, smem_gru>>>(mask, w_hh_lr, b_hh_lr,
                                               w_hh_rl, b_hh_rl, out);
}

// round 8
// speedup vs baseline: 1.1727x; 1.1727x over previous
#include <cuda_runtime.h>
#include <cuda_bf16.h>
#include <cstdint>
#include <math.h>

#define B_   64
#define L_   1024
#define IN_  512
#define H_   512
#define G3_  1536
#define NBLK 128
#define NTOT 65536   // L_ * B_

// ---------------------------------------------------------------------------
// Device-global scratch (allocation APIs are forbidden)
// ---------------------------------------------------------------------------
__device__ float g_gx[(size_t)2 * G3_ * NTOT];        // [d][m][n=t*64+b]  805 MB
__device__ float g_hbuf[2 * 2 * H_ * B_];             // [d][buf][k][b]
__device__ unsigned g_cnt = 0;
__device__ unsigned g_gen = 0;
__device__ __nv_bfloat16 g_xs[2][(size_t)L_ * B_ * IN_];      // [split][t*64+b][k]
__device__ __nv_bfloat16 g_ws[2][2][(size_t)G3_ * IN_];       // [d][split][m][k]

// ---------------------------------------------------------------------------
// Warp-level tensor-core helpers (base-arch legal: ldmatrix + mma.sync)
// ---------------------------------------------------------------------------
static __device__ __forceinline__ uint32_t smem_u32(const void* p) {
    uint32_t a;
    asm("{ .reg .u64 t; cvta.to.shared.u64 t, %1; cvt.u32.u64 %0, t; }" : "=r"(a) : "l"(p));
    return a;
}
static __device__ __forceinline__ void ldsm4(uint32_t* r, uint32_t addr) {
    asm volatile("ldmatrix.sync.aligned.m8n8.x4.shared.b16 {%0,%1,%2,%3}, [%4];"
                 : "=r"(r[0]), "=r"(r[1]), "=r"(r[2]), "=r"(r[3]) : "r"(addr));
}
static __device__ __forceinline__ void mma16816(float* c, const uint32_t* a,
                                                uint32_t b0, uint32_t b1) {
    asm volatile(
        "mma.sync.aligned.m16n8k16.row.col.f32.bf16.bf16.f32 "
        "{%0,%1,%2,%3}, {%4,%5,%6,%7}, {%8,%9}, {%0,%1,%2,%3};"
        : "+f"(c[0]), "+f"(c[1]), "+f"(c[2]), "+f"(c[3])
        : "r"(a[0]), "r"(a[1]), "r"(a[2]), "r"(a[3]), "r"(b0), "r"(b1));
}

// ---------------------------------------------------------------------------
// Split kernels: fp32 -> bf16 hi/lo pairs
// ---------------------------------------------------------------------------
static __device__ __forceinline__ void split4(float4 v, __nv_bfloat162* ph,
                                              __nv_bfloat162* pl) {
    __nv_bfloat16 h0 = __float2bfloat16(v.x), h1 = __float2bfloat16(v.y);
    __nv_bfloat16 h2 = __float2bfloat16(v.z), h3 = __float2bfloat16(v.w);
    __nv_bfloat16 l0 = __float2bfloat16(v.x - __bfloat162float(h0));
    __nv_bfloat16 l1 = __float2bfloat16(v.y - __bfloat162float(h1));
    __nv_bfloat16 l2 = __float2bfloat16(v.z - __bfloat162float(h2));
    __nv_bfloat16 l3 = __float2bfloat16(v.w - __bfloat162float(h3));
    __nv_bfloat162 t;
    t.x = h0; t.y = h1; ph[0] = t;  t.x = h2; t.y = h3; ph[1] = t;
    t.x = l0; t.y = l1; pl[0] = t;  t.x = l2; t.y = l3; pl[1] = t;
}

// g_xs[split][(t*64+b)*512 + k]  (time-major rows)
__global__ __launch_bounds__(256) void split_x_kernel(const float* __restrict__ feats) {
    const int t = blockIdx.x;
    for (int i = threadIdx.x; i < 8192; i += 256) {
        const int b = i >> 7, q = i & 127;                 // q: float4 index in k
        float4 v = ((const float4*)feats)[((size_t)b * 1024 + t) * 128 + q];
        const size_t base = ((size_t)t * 64 + b) * 512 + q * 4;
        split4(v, (__nv_bfloat162*)&g_xs[0][base], (__nv_bfloat162*)&g_xs[1][base]);
    }
}

__global__ __launch_bounds__(256) void split_w_kernel(const float* __restrict__ wlr,
                                                      const float* __restrict__ wrl) {
    const size_t n4 = (size_t)G3_ * IN_ / 4;
    for (size_t i = blockIdx.x * (size_t)blockDim.x + threadIdx.x; i < 2 * n4;
         i += (size_t)gridDim.x * blockDim.x) {
        const int d = i >= n4;
        const size_t j = d ? (i - n4) : i;
        float4 v = ((const float4*)(d ? wrl : wlr))[j];
        split4(v, (__nv_bfloat162*)&g_ws[d][0][j * 4], (__nv_bfloat162*)&g_ws[d][1][j * 4]);
    }
}

// ---------------------------------------------------------------------------
// HMMA projection: gx[d][m][n] = sum_k W[d][m][k] * X[n][k] + b_ih[d][m]
// Block 128m x 128n, 256 thr (8 warps: wm=wid&3 -> 32m, wn=wid>>2 -> 64n),
// k chunks of 32, double-buffered smem (80B row pitch), bf16x3 split.
// smem stage: AH(10240) AL(10240) BH(10240) BL(10240) = 40960B, x2 = 81920B.
// ---------------------------------------------------------------------------
#define PROJ_SMEM 81920

__global__ __launch_bounds__(256) void proj_mma(const float* __restrict__ b_ih_lr,
                                                const float* __restrict__ b_ih_rl)
{
    extern __shared__ char smc[];
    const uint32_t sb = smem_u32(smc);
    const int tid = threadIdx.x, wid = tid >> 5, lid = tid & 31;
    const int wm = wid & 3, wn = wid >> 2;
    const int m0 = blockIdx.x * 128, n0 = blockIdx.y * 128, d = blockIdx.z;

    const __nv_bfloat16* wh = &g_ws[d][0][(size_t)m0 * 512];
    const __nv_bfloat16* wl = &g_ws[d][1][(size_t)m0 * 512];

    // ---- loader addressing: 2 rows per thread per tile (rows ar, ar+64) ----
    const int q  = tid & 3;          // 16B chunk within 32-k row (4 chunks)
    const int ar = tid >> 2;         // 0..63
    const size_t aOff0 = (size_t)ar * 512 + q * 8;
    const size_t aOff1 = (size_t)(ar + 64) * 512 + q * 8;
    const int nA0 = n0 + ar, nA1 = n0 + ar + 64;
    const size_t bSrc0 = ((size_t)(d ? ((1023 - (nA0 >> 6)) * 64 + (nA0 & 63)) : nA0)) * 512 + q * 8;
    const size_t bSrc1 = ((size_t)(d ? ((1023 - (nA1 >> 6)) * 64 + (nA1 & 63)) : nA1)) * 512 + q * 8;
    const uint32_t sO0 = (uint32_t)(ar * 80 + q * 16);
    const uint32_t sO1 = (uint32_t)((ar + 64) * 80 + q * 16);

    // ---- ldmatrix lane bases ----
    const int mld = lid >> 3, lr8 = lid & 7;
    const uint32_t aBase = sb +
        (uint32_t)((wm * 32 + ((mld & 1) << 3) + lr8) * 80 + (((mld >> 1) << 3) << 1));
    const uint32_t bBase = sb + 20480u +
        (uint32_t)((wn * 64 + ((mld >> 1) << 3) + lr8) * 80 + (((mld & 1) << 3) << 1));

    float acc[2][8][4];
    #pragma unroll
    for (int f = 0; f < 2; ++f)
        #pragma unroll
        for (int nf = 0; nf < 8; ++nf)
            #pragma unroll
            for (int e = 0; e < 4; ++e) acc[f][nf][e] = 0.f;

    uint4 pAh0, pAh1, pAl0, pAl1, pBh0, pBh1, pBl0, pBl1;
    // prefetch kc = 0
    pAh0 = *(const uint4*)(wh + aOff0);  pAh1 = *(const uint4*)(wh + aOff1);
    pAl0 = *(const uint4*)(wl + aOff0);  pAl1 = *(const uint4*)(wl + aOff1);
    pBh0 = *(const uint4*)(&g_xs[0][bSrc0]);  pBh1 = *(const uint4*)(&g_xs[0][bSrc1]);
    pBl0 = *(const uint4*)(&g_xs[1][bSrc0]);  pBl1 = *(const uint4*)(&g_xs[1][bSrc1]);

    int s = 0;
    for (int kc = 0; kc < 512; kc += 32) {
        char* base = smc + s * 40960;
        *(uint4*)(base + sO0)          = pAh0;  *(uint4*)(base + sO1)          = pAh1;
        *(uint4*)(base + 10240 + sO0)  = pAl0;  *(uint4*)(base + 10240 + sO1)  = pAl1;
        *(uint4*)(base + 20480 + sO0)  = pBh0;  *(uint4*)(base + 20480 + sO1)  = pBh1;
        *(uint4*)(base + 30720 + sO0)  = pBl0;  *(uint4*)(base + 30720 + sO1)  = pBl1;
        __syncthreads();

        if (kc + 32 < 512) {   // prefetch next chunk (overlaps MMA below)
            const int kn = kc + 32;
            pAh0 = *(const uint4*)(wh + aOff0 + kn);  pAh1 = *(const uint4*)(wh + aOff1 + kn);
            pAl0 = *(const uint4*)(wl + aOff0 + kn);  pAl1 = *(const uint4*)(wl + aOff1 + kn);
            pBh0 = *(const uint4*)(&g_xs[0][bSrc0 + kn]);
            pBh1 = *(const uint4*)(&g_xs[0][bSrc1 + kn]);
            pBl0 = *(const uint4*)(&g_xs[1][bSrc0 + kn]);
            pBl1 = *(const uint4*)(&g_xs[1][bSrc1 + kn]);
        }

        const uint32_t so = (uint32_t)(s * 40960);
        #pragma unroll
        for (int j = 0; j < 2; ++j) {                       // two k16 steps
            const uint32_t ko = so + j * 32;
            uint32_t Ah[2][4], Al[2][4];
            ldsm4(Ah[0], aBase + ko);
            ldsm4(Ah[1], aBase + ko + 1280);
            ldsm4(Al[0], aBase + ko + 10240);
            ldsm4(Al[1], aBase + ko + 10240 + 1280);
            #pragma unroll
            for (int p = 0; p < 4; ++p) {
                uint32_t bh[4], bl[4];
                ldsm4(bh, bBase + ko + p * 1280);
                ldsm4(bl, bBase + ko + p * 1280 + 10240);
                #pragma unroll
                for (int f = 0; f < 2; ++f) {
                    mma16816(acc[f][2 * p],     Ah[f], bh[0], bh[1]);
                    mma16816(acc[f][2 * p],     Ah[f], bl[0], bl[1]);
                    mma16816(acc[f][2 * p],     Al[f], bh[0], bh[1]);
                    mma16816(acc[f][2 * p + 1], Ah[f], bh[2], bh[3]);
                    mma16816(acc[f][2 * p + 1], Ah[f], bl[2], bl[3]);
                    mma16816(acc[f][2 * p + 1], Al[f], bh[2], bh[3]);
                }
            }
        }
        s ^= 1;
    }

    // ---- epilogue: bias + store ----
    const int r0 = lid >> 2, c2 = (lid & 3) * 2;
    const float* bias = d ? b_ih_rl : b_ih_lr;
    #pragma unroll
    for (int f = 0; f < 2; ++f) {
        const int mr = m0 + wm * 32 + f * 16 + r0;
        const float bz0 = bias[mr], bz1 = bias[mr + 8];
        float* row0 = &g_gx[((size_t)d * G3_ + mr) * NTOT];
        float* row1 = row0 + (size_t)8 * NTOT;
        #pragma unroll
        for (int nf = 0; nf < 8; ++nf) {
            const int nc = n0 + wn * 64 + nf * 8 + c2;
            float2 v0, v1;
            v0.x = acc[f][nf][0] + bz0;  v0.y = acc[f][nf][1] + bz0;
            v1.x = acc[f][nf][2] + bz1;  v1.y = acc[f][nf][3] + bz1;
            *(float2*)&row0[nc] = v0;
            *(float2*)&row1[nc] = v1;
        }
    }
}

// ---------------------------------------------------------------------------
// Grid barrier across all NBLK blocks (self-resetting, graph-replay safe).
// ---------------------------------------------------------------------------
__device__ __forceinline__ void grid_bar()
{
    __syncthreads();
    if (threadIdx.x == 0) {
        __threadfence();
        volatile unsigned* vgen = &g_gen;
        const unsigned snap = *vgen;
        const unsigned old  = atomicAdd(&g_cnt, 1);
        if (old == NBLK - 1) {
            g_cnt = 0;
            __threadfence();
            atomicAdd(&g_gen, 1);
        } else {
            while (*vgen == snap) { __nanosleep(64); }
        }
        __threadfence();
    }
    __syncthreads();
}

// ---------------------------------------------------------------------------
// Persistent fp32 recurrence (validated round-2 logic; gx addressed [d][m][n])
// ---------------------------------------------------------------------------
__global__ void __launch_bounds__(512, 1) gru_kernel(
    const float* __restrict__ mask,
    const float* __restrict__ w_hh_lr, const float* __restrict__ b_hh_lr,
    const float* __restrict__ w_hh_rl, const float* __restrict__ b_hh_rl,
    float* __restrict__ out)
{
    extern __shared__ float smf[];
    float* hs   = smf;            // 32768 floats: hs[k*64 + b]
    float* ws   = smf + 32768;    // 12288 floats: ws[(gate*8+g)*512 + k]
    float* red  = smf + 45056;    // 1536  floats
    float* hout = smf + 46592;    // 512   floats

    const int d  = blockIdx.y;
    const int c0 = blockIdx.x * 8;
    const float* whh = d ? w_hh_rl : w_hh_lr;
    const float* bhh = d ? b_hh_rl : b_hh_lr;

    const int tid = threadIdx.x;
    const int bh  = tid & 31;
    const int gi  = (tid >> 5) & 7;
    const int kh  = tid >> 8;

    for (int i = tid; i < 3072; i += 512) {
        const int fi   = i << 2;
        const int row  = fi >> 9;
        const int k    = fi & 511;
        const int gate = row >> 3, g = row & 7;
        *(float4*)&ws[fi] =
            *(const float4*)&whh[((size_t)(gate * H_ + c0 + g)) * H_ + k];
    }
    {
        const int gg = tid >> 6, b = tid & 63;
        g_hbuf[((d * 2 + 0) * H_ + c0 + gg) * B_ + b] = 0.f;
    }
    grid_bar();

    const float* wr = &ws[(0 * 8 + gi) * 512];
    const float* wz = &ws[(1 * 8 + gi) * 512];
    const float* wn = &ws[(2 * 8 + gi) * 512];
    const int k0 = kh << 8;

    for (int t = 0; t < L_; ++t) {
        const int cur = t & 1, nxt = cur ^ 1;

        const float4* hsrc = (const float4*)&g_hbuf[(d * 2 + cur) * H_ * B_];
        float4* hdst = (float4*)hs;
        #pragma unroll
        for (int i = 0; i < 16; ++i)
            hdst[tid + i * 512] = hsrc[tid + i * 512];
        __syncthreads();

        float ar0 = 0.f, az0 = 0.f, an0 = 0.f;
        float ar1 = 0.f, az1 = 0.f, an1 = 0.f;
        #pragma unroll 8
        for (int k = k0; k < k0 + 256; k += 4) {
            const float4 wrv = *(const float4*)&wr[k];
            const float4 wzv = *(const float4*)&wz[k];
            const float4 wnv = *(const float4*)&wn[k];
            const float* hp = &hs[k * 64 + bh];
            float ha, hb;
            ha = hp[0];   hb = hp[32];
            ar0 += wrv.x * ha; az0 += wzv.x * ha; an0 += wnv.x * ha;
            ar1 += wrv.x * hb; az1 += wzv.x * hb; an1 += wnv.x * hb;
            ha = hp[64];  hb = hp[96];
            ar0 += wrv.y * ha; az0 += wzv.y * ha; an0 += wnv.y * ha;
            ar1 += wrv.y * hb; az1 += wzv.y * hb; an1 += wnv.y * hb;
            ha = hp[128]; hb = hp[160];
            ar0 += wrv.z * ha; az0 += wzv.z * ha; an0 += wnv.z * ha;
            ar1 += wrv.z * hb; az1 += wzv.z * hb; an1 += wnv.z * hb;
            ha = hp[192]; hb = hp[224];
            ar0 += wrv.w * ha; az0 += wzv.w * ha; an0 += wnv.w * ha;
            ar1 += wrv.w * hb; az1 += wzv.w * hb; an1 += wnv.w * hb;
        }

        if (kh) {
            float* r0 = &red[(gi * 64 + bh) * 3];
            r0[0] = ar0; r0[1] = az0; r0[2] = an0;
            float* r1 = &red[(gi * 64 + bh + 32) * 3];
            r1[0] = ar1; r1[1] = az1; r1[2] = an1;
        }
        __syncthreads();

        if (!kh) {
            const int te = d ? (1023 - t) : t;
            const size_t gxb = (size_t)d * G3_ * NTOT + (size_t)t * 64;
            const int cg = c0 + gi;
            const float br = bhh[cg], bz = bhh[H_ + cg], bn = bhh[2 * H_ + cg];
            #pragma unroll
            for (int p = 0; p < 2; ++p) {
                const int b = bh + p * 32;
                const float* rr = &red[(gi * 64 + b) * 3];
                const float hr = (p ? ar1 : ar0) + rr[0] + br;
                const float hz = (p ? az1 : az0) + rr[1] + bz;
                const float hn = (p ? an1 : an0) + rr[2] + bn;
                const float xr = g_gx[gxb + (size_t)cg * NTOT + b];
                const float xz = g_gx[gxb + (size_t)(H_ + cg) * NTOT + b];
                const float xn = g_gx[gxb + (size_t)(2 * H_ + cg) * NTOT + b];
                const float r = 1.f / (1.f + expf(-(xr + hr)));
                const float z = 1.f / (1.f + expf(-(xz + hz)));
                const float n = tanhf(xn + r * hn);
                const float hprev = hs[cg * 64 + b];
                const float hnew  = (1.f - z) * n + z * hprev;
                const float mk = mask[(size_t)b * L_ + te];
                const float h  = mk * hnew + (1.f - mk) * hprev;
                g_hbuf[((d * 2 + nxt) * H_ + cg) * B_ + b] = h;
                hout[b * 8 + gi] = h;
            }
        }
        __syncthreads();

        if (tid < 64) {
            const int b = tid;
            const int l = d ? (1023 - t) : t;
            float4* dst = (float4*)&out[((size_t)b * L_ + l) * 1024 + d * H_ + c0];
            dst[0] = *(float4*)&hout[b * 8];
            dst[1] = *(float4*)&hout[b * 8 + 4];
        }
        grid_bar();
    }
}

// ---------------------------------------------------------------------------
extern "C" void kernel_launch(void* const* d_in, const int* in_sizes, int n_in,
                              void* d_out, int out_size)
{
    const float* feats   = (const float*)d_in[0];
    const float* mask    = (const float*)d_in[1];
    const float* w_ih_lr = (const float*)d_in[2];
    const float* w_hh_lr = (const float*)d_in[3];
    const float* b_ih_lr = (const float*)d_in[4];
    const float* b_hh_lr = (const float*)d_in[5];
    const float* w_ih_rl = (const float*)d_in[6];
    const float* w_hh_rl = (const float*)d_in[7];
    const float* b_ih_rl = (const float*)d_in[8];
    const float* b_hh_rl = (const float*)d_in[9];
    float* out = (float*)d_out;

    const int smem_gru = (32768 + 12288 + 1536 + 512) * 4;  // 188416 B
    cudaFuncSetAttribute(gru_kernel, cudaFuncAttributeMaxDynamicSharedMemorySize, smem_gru);
    cudaFuncSetAttribute(proj_mma, cudaFuncAttributeMaxDynamicSharedMemorySize, PROJ_SMEM);

    split_x_kernel<<<1024, 256>>>(feats);
    split_w_kernel<<<1536, 256>>>(w_ih_lr, w_ih_rl);
    proj_mma<<<dim3(12, 512, 2), 256, PROJ_SMEM>>>(b_ih_lr, b_ih_rl);
    gru_kernel<<<dim3(64, 2), 512, smem_gru>>>(mask, w_hh_lr, b_hh_lr,
                                               w_hh_rl, b_hh_rl, out);
}

// round 13
// speedup vs baseline: 1.7044x; 1.4534x over previous
#include <cuda_runtime.h>
#include <cuda_bf16.h>
#include <cstdint>
#include <math.h>

#define B_   64
#define L_   1024
#define IN_  512
#define H_   512
#define G3_  1536
#define NBLK 128
#define NTOT 65536   // L_ * B_

// ---------------------------------------------------------------------------
// Device-global scratch (allocation APIs are forbidden)
// ---------------------------------------------------------------------------
__device__ float g_gx[(size_t)2 * G3_ * NTOT];        // [d][m][n=t*64+b]  805 MB
__device__ unsigned g_cnt = 0;
__device__ unsigned g_gen = 0;
__device__ __nv_bfloat16 g_xs[2][(size_t)L_ * B_ * IN_];      // [split][t*64+b][k]
__device__ __nv_bfloat16 g_ws[2][2][(size_t)G3_ * IN_];       // [d][split][m][k]
// h carry: [d][buf][split][b*512 + k]  bf16 hi/lo, double buffered
__device__ __align__(16) __nv_bfloat16 g_h16t[2 * 2 * 2 * 32768];

// ---------------------------------------------------------------------------
// Warp-level tensor-core helpers (base-arch legal: ldmatrix + mma.sync)
// ---------------------------------------------------------------------------
static __device__ __forceinline__ uint32_t smem_u32(const void* p) {
    uint32_t a;
    asm("{ .reg .u64 t; cvta.to.shared.u64 t, %1; cvt.u32.u64 %0, t; }" : "=r"(a) : "l"(p));
    return a;
}
static __device__ __forceinline__ void ldsm4(uint32_t* r, uint32_t addr) {
    asm volatile("ldmatrix.sync.aligned.m8n8.x4.shared.b16 {%0,%1,%2,%3}, [%4];"
                 : "=r"(r[0]), "=r"(r[1]), "=r"(r[2]), "=r"(r[3]) : "r"(addr));
}
static __device__ __forceinline__ void mma16816(float* c, const uint32_t* a,
                                                uint32_t b0, uint32_t b1) {
    asm volatile(
        "mma.sync.aligned.m16n8k16.row.col.f32.bf16.bf16.f32 "
        "{%0,%1,%2,%3}, {%4,%5,%6,%7}, {%8,%9}, {%0,%1,%2,%3};"
        : "+f"(c[0]), "+f"(c[1]), "+f"(c[2]), "+f"(c[3])
        : "r"(a[0]), "r"(a[1]), "r"(a[2]), "r"(a[3]), "r"(b0), "r"(b1));
}
#define CP_ASYNC16(dst, src) \
    asm volatile("cp.async.cg.shared.global [%0], [%1], 16;" :: "r"(dst), "l"(src))
#define CP_COMMIT asm volatile("cp.async.commit_group;" ::: "memory")
#define CP_WAIT0  asm volatile("cp.async.wait_group 0;" ::: "memory")

// ---------------------------------------------------------------------------
// Split kernels: fp32 -> bf16 hi/lo pairs
// ---------------------------------------------------------------------------
static __device__ __forceinline__ void split4(float4 v, __nv_bfloat162* ph,
                                              __nv_bfloat162* pl) {
    __nv_bfloat16 h0 = __float2bfloat16(v.x), h1 = __float2bfloat16(v.y);
    __nv_bfloat16 h2 = __float2bfloat16(v.z), h3 = __float2bfloat16(v.w);
    __nv_bfloat16 l0 = __float2bfloat16(v.x - __bfloat162float(h0));
    __nv_bfloat16 l1 = __float2bfloat16(v.y - __bfloat162float(h1));
    __nv_bfloat16 l2 = __float2bfloat16(v.z - __bfloat162float(h2));
    __nv_bfloat16 l3 = __float2bfloat16(v.w - __bfloat162float(h3));
    __nv_bfloat162 t;
    t.x = h0; t.y = h1; ph[0] = t;  t.x = h2; t.y = h3; ph[1] = t;
    t.x = l0; t.y = l1; pl[0] = t;  t.x = l2; t.y = l3; pl[1] = t;
}

__global__ __launch_bounds__(256) void split_x_kernel(const float* __restrict__ feats) {
    const int t = blockIdx.x;
    for (int i = threadIdx.x; i < 8192; i += 256) {
        const int b = i >> 7, q = i & 127;
        float4 v = ((const float4*)feats)[((size_t)b * 1024 + t) * 128 + q];
        const size_t base = ((size_t)t * 64 + b) * 512 + q * 4;
        split4(v, (__nv_bfloat162*)&g_xs[0][base], (__nv_bfloat162*)&g_xs[1][base]);
    }
}

__global__ __launch_bounds__(256) void split_w_kernel(const float* __restrict__ wlr,
                                                      const float* __restrict__ wrl) {
    const size_t n4 = (size_t)G3_ * IN_ / 4;
    for (size_t i = blockIdx.x * (size_t)blockDim.x + threadIdx.x; i < 2 * n4;
         i += (size_t)gridDim.x * blockDim.x) {
        const int d = i >= n4;
        const size_t j = d ? (i - n4) : i;
        float4 v = ((const float4*)(d ? wrl : wlr))[j];
        split4(v, (__nv_bfloat162*)&g_ws[d][0][j * 4], (__nv_bfloat162*)&g_ws[d][1][j * 4]);
    }
}

// ---------------------------------------------------------------------------
// HMMA projection (reordered MMA passes to break accumulator RAW chains)
// ---------------------------------------------------------------------------
#define PROJ_SMEM 81920

__global__ __launch_bounds__(256) void proj_mma(const float* __restrict__ b_ih_lr,
                                                const float* __restrict__ b_ih_rl)
{
    extern __shared__ char smc[];
    const uint32_t sb = smem_u32(smc);
    const int tid = threadIdx.x, wid = tid >> 5, lid = tid & 31;
    const int wm = wid & 3, wn = wid >> 2;
    const int m0 = blockIdx.x * 128, n0 = blockIdx.y * 128, d = blockIdx.z;

    const __nv_bfloat16* wh = &g_ws[d][0][(size_t)m0 * 512];
    const __nv_bfloat16* wl = &g_ws[d][1][(size_t)m0 * 512];

    const int q  = tid & 3;
    const int ar = tid >> 2;
    const size_t aOff0 = (size_t)ar * 512 + q * 8;
    const size_t aOff1 = (size_t)(ar + 64) * 512 + q * 8;
    const int nA0 = n0 + ar, nA1 = n0 + ar + 64;
    const size_t bSrc0 = ((size_t)(d ? ((1023 - (nA0 >> 6)) * 64 + (nA0 & 63)) : nA0)) * 512 + q * 8;
    const size_t bSrc1 = ((size_t)(d ? ((1023 - (nA1 >> 6)) * 64 + (nA1 & 63)) : nA1)) * 512 + q * 8;
    const uint32_t sO0 = (uint32_t)(ar * 80 + q * 16);
    const uint32_t sO1 = (uint32_t)((ar + 64) * 80 + q * 16);

    const int mld = lid >> 3, lr8 = lid & 7;
    const uint32_t aBase = sb +
        (uint32_t)((wm * 32 + ((mld & 1) << 3) + lr8) * 80 + (((mld >> 1) << 3) << 1));
    const uint32_t bBase = sb + 20480u +
        (uint32_t)((wn * 64 + ((mld >> 1) << 3) + lr8) * 80 + (((mld & 1) << 3) << 1));

    float acc[2][8][4];
    #pragma unroll
    for (int f = 0; f < 2; ++f)
        #pragma unroll
        for (int nf = 0; nf < 8; ++nf)
            #pragma unroll
            for (int e = 0; e < 4; ++e) acc[f][nf][e] = 0.f;

    uint4 pAh0, pAh1, pAl0, pAl1, pBh0, pBh1, pBl0, pBl1;
    pAh0 = *(const uint4*)(wh + aOff0);  pAh1 = *(const uint4*)(wh + aOff1);
    pAl0 = *(const uint4*)(wl + aOff0);  pAl1 = *(const uint4*)(wl + aOff1);
    pBh0 = *(const uint4*)(&g_xs[0][bSrc0]);  pBh1 = *(const uint4*)(&g_xs[0][bSrc1]);
    pBl0 = *(const uint4*)(&g_xs[1][bSrc0]);  pBl1 = *(const uint4*)(&g_xs[1][bSrc1]);

    int s = 0;
    for (int kc = 0; kc < 512; kc += 32) {
        char* base = smc + s * 40960;
        *(uint4*)(base + sO0)          = pAh0;  *(uint4*)(base + sO1)          = pAh1;
        *(uint4*)(base + 10240 + sO0)  = pAl0;  *(uint4*)(base + 10240 + sO1)  = pAl1;
        *(uint4*)(base + 20480 + sO0)  = pBh0;  *(uint4*)(base + 20480 + sO1)  = pBh1;
        *(uint4*)(base + 30720 + sO0)  = pBl0;  *(uint4*)(base + 30720 + sO1)  = pBl1;
        __syncthreads();

        if (kc + 32 < 512) {
            const int kn = kc + 32;
            pAh0 = *(const uint4*)(wh + aOff0 + kn);  pAh1 = *(const uint4*)(wh + aOff1 + kn);
            pAl0 = *(const uint4*)(wl + aOff0 + kn);  pAl1 = *(const uint4*)(wl + aOff1 + kn);
            pBh0 = *(const uint4*)(&g_xs[0][bSrc0 + kn]);
            pBh1 = *(const uint4*)(&g_xs[0][bSrc1 + kn]);
            pBl0 = *(const uint4*)(&g_xs[1][bSrc0 + kn]);
            pBl1 = *(const uint4*)(&g_xs[1][bSrc1 + kn]);
        }

        const uint32_t so = (uint32_t)(s * 40960);
        #pragma unroll
        for (int j = 0; j < 2; ++j) {
            const uint32_t ko = so + j * 32;
            uint32_t Ah[2][4], Al[2][4], Bh[4][4], Bl[4][4];
            ldsm4(Ah[0], aBase + ko);
            ldsm4(Ah[1], aBase + ko + 1280);
            ldsm4(Al[0], aBase + ko + 10240);
            ldsm4(Al[1], aBase + ko + 10240 + 1280);
            #pragma unroll
            for (int p = 0; p < 4; ++p) {
                ldsm4(Bh[p], bBase + ko + p * 1280);
                ldsm4(Bl[p], bBase + ko + p * 1280 + 10240);
            }
            #pragma unroll
            for (int p = 0; p < 4; ++p)
                #pragma unroll
                for (int f = 0; f < 2; ++f) {
                    mma16816(acc[f][2 * p],     Ah[f], Bh[p][0], Bh[p][1]);
                    mma16816(acc[f][2 * p + 1], Ah[f], Bh[p][2], Bh[p][3]);
                }
            #pragma unroll
            for (int p = 0; p < 4; ++p)
                #pragma unroll
                for (int f = 0; f < 2; ++f) {
                    mma16816(acc[f][2 * p],     Al[f], Bh[p][0], Bh[p][1]);
                    mma16816(acc[f][2 * p + 1], Al[f], Bh[p][2], Bh[p][3]);
                }
            #pragma unroll
            for (int p = 0; p < 4; ++p)
                #pragma unroll
                for (int f = 0; f < 2; ++f) {
                    mma16816(acc[f][2 * p],     Ah[f], Bl[p][0], Bl[p][1]);
                    mma16816(acc[f][2 * p + 1], Ah[f], Bl[p][2], Bl[p][3]);
                }
        }
        s ^= 1;
    }

    const int r0 = lid >> 2, c2 = (lid & 3) * 2;
    const float* bias = d ? b_ih_rl : b_ih_lr;
    #pragma unroll
    for (int f = 0; f < 2; ++f) {
        const int mr = m0 + wm * 32 + f * 16 + r0;
        const float bz0 = bias[mr], bz1 = bias[mr + 8];
        float* row0 = &g_gx[((size_t)d * G3_ + mr) * NTOT];
        float* row1 = row0 + (size_t)8 * NTOT;
        #pragma unroll
        for (int nf = 0; nf < 8; ++nf) {
            const int nc = n0 + wn * 64 + nf * 8 + c2;
            float2 v0, v1;
            v0.x = acc[f][nf][0] + bz0;  v0.y = acc[f][nf][1] + bz0;
            v1.x = acc[f][nf][2] + bz1;  v1.y = acc[f][nf][3] + bz1;
            *(float2*)&row0[nc] = v0;
            *(float2*)&row1[nc] = v1;
        }
    }
}

// ---------------------------------------------------------------------------
// Grid barrier across all NBLK blocks (self-resetting, graph-replay safe).
// ---------------------------------------------------------------------------
__device__ __forceinline__ void grid_bar()
{
    __syncthreads();
    if (threadIdx.x == 0) {
        __threadfence();
        volatile unsigned* vgen = &g_gen;
        const unsigned snap = *vgen;
        const unsigned old  = atomicAdd(&g_cnt, 1);
        if (old == NBLK - 1) {
            g_cnt = 0;
            __threadfence();
            atomicAdd(&g_gen, 1);
        } else {
            while (*vgen == snap) { __nanosleep(64); }
        }
        __threadfence();
    }
    __syncthreads();
}

// ---------------------------------------------------------------------------
// HMMA persistent recurrence.
// Grid (64, 2): block = (8 hidden cols, dir), 512 thr = 16 warps = 4m x 4k.
// smem layout (bytes):
//   hsH h-hi  [64 b][pitch 1040]      0      .. 66560
//   hsL h-lo                          66560  .. 133120
//   wsH W-hi  [24 n][pitch 1040]      133120 .. 158080
//   wsL W-lo                          158080 .. 183040
//   red [ki4][n24][66 words] f32      183040 .. 208384
//   hout[512] f32                     208384 .. 210432
// ---------------------------------------------------------------------------
#define GRU_SMEM 210432

__global__ void __launch_bounds__(512, 1) gru_mma(
    const float* __restrict__ mask,
    const float* __restrict__ w_hh_lr, const float* __restrict__ b_hh_lr,
    const float* __restrict__ w_hh_rl, const float* __restrict__ b_hh_rl,
    float* __restrict__ out)
{
    extern __shared__ char smc[];
    const uint32_t sb = smem_u32(smc);
    float* red  = (float*)(smc + 183040);
    float* hout = (float*)(smc + 208384);
    __nv_bfloat16* wsH16 = (__nv_bfloat16*)(smc + 133120);
    __nv_bfloat16* wsL16 = (__nv_bfloat16*)(smc + 158080);

    const int d  = blockIdx.y;
    const int c0 = blockIdx.x * 8;
    const float* whh = d ? w_hh_rl : w_hh_lr;
    const float* bhh = d ? b_hh_rl : b_hh_lr;

    const int tid = threadIdx.x, wid = tid >> 5, lid = tid & 31;
    const int mi = wid & 3, ki = wid >> 2;
    const int lr8 = lid & 7, mld = lid >> 3;
    const int col = tid >> 6, bb = tid & 63;   // pointwise ownership (col, batch)
    const int gt  = tid & 127;                 // id within ki-group

    // ---- stage W (fp32 -> bf16 hi/lo) into smem ----
    for (int i = tid; i < 12288; i += 512) {
        const int n = i >> 9, k = i & 511;
        const float w = whh[((size_t)((n >> 3) * 512 + c0 + (n & 7))) * 512 + k];
        const __nv_bfloat16 hi = __float2bfloat16(w);
        wsH16[n * 520 + k] = hi;
        wsL16[n * 520 + k] = __float2bfloat16(w - __bfloat162float(hi));
    }
    // ---- zero h16 buffer 0 (this block's cols) ----
    {
        const size_t base = (size_t)(d * 2 + 0) * 2 * 32768;
        g_h16t[base + bb * 512 + c0 + col]         = __float2bfloat16(0.f);
        g_h16t[base + 32768 + bb * 512 + c0 + col] = __float2bfloat16(0.f);
    }
    float hprev = 0.f;
    const float br  = bhh[c0 + col];
    const float bz2 = bhh[512 + c0 + col];
    const float bn2 = bhh[1024 + c0 + col];
    __syncthreads();
    grid_bar();

    // ---- ldsm bases ----
    const uint32_t aBaseH = sb + (uint32_t)((mi * 16 + (mld & 1) * 8 + lr8) * 1040
                                            + (mld >> 1) * 16 + ki * 256);
    const uint32_t aBaseL = aBaseH + 66560u;
    const uint32_t bBaseH = sb + 133120u + (uint32_t)(lr8 * 1040 + ki * 256 + mld * 16);
    const uint32_t bBaseL = bBaseH + 24960u;

    for (int t = 0; t < L_; ++t) {
        const int cur = t & 1, nxt = cur ^ 1;

        // ---- stage h[cur] k-slice (each ki-group loads its 256B window) ----
        const size_t hb = (size_t)(d * 2 + cur) * 2 * 32768;
        #pragma unroll
        for (int it = 0; it < 8; ++it) {
            const int idx = gt + it * 128;
            const int rb = idx >> 4, qq = idx & 15;
            const uint32_t dst = sb + (uint32_t)(rb * 1040 + ki * 256 + qq * 16);
            const __nv_bfloat16* src = &g_h16t[hb + rb * 512 + ki * 128 + qq * 8];
            CP_ASYNC16(dst, src);
            CP_ASYNC16(dst + 66560u, src + 32768);
        }
        CP_COMMIT;

        const int te = d ? (1023 - t) : t;
        const size_t gxn = (size_t)t * 64 + bb;
        const float xr  = g_gx[((size_t)d * G3_ + c0 + col) * NTOT + gxn];
        const float xz  = g_gx[((size_t)d * G3_ + 512 + c0 + col) * NTOT + gxn];
        const float xn_ = g_gx[((size_t)d * G3_ + 1024 + c0 + col) * NTOT + gxn];
        const float mk  = mask[(size_t)bb * 1024 + te];

        CP_WAIT0;
        __syncthreads();   // single block-wide sync (named barriers removed)

        // ---- MMA: m16 (mi) x n24 x k128 (ki), bf16x3 split ----
        float acc[3][4];
        #pragma unroll
        for (int nt = 0; nt < 3; ++nt) {
            acc[nt][0] = 0.f; acc[nt][1] = 0.f; acc[nt][2] = 0.f; acc[nt][3] = 0.f;
        }
        uint32_t bh[3][4], bl[3][4];
        #pragma unroll
        for (int kt = 0; kt < 8; ++kt) {
            if ((kt & 1) == 0) {
                const uint32_t ko = (uint32_t)((kt >> 1) * 64);
                #pragma unroll
                for (int nt = 0; nt < 3; ++nt) {
                    ldsm4(bh[nt], bBaseH + nt * 8320u + ko);
                    ldsm4(bl[nt], bBaseL + nt * 8320u + ko);
                }
            }
            uint32_t Ah[4], Al[4];
            ldsm4(Ah, aBaseH + kt * 32);
            ldsm4(Al, aBaseL + kt * 32);
            const int kp = (kt & 1) * 2;
            #pragma unroll
            for (int nt = 0; nt < 3; ++nt)
                mma16816(acc[nt], Ah, bh[nt][kp], bh[nt][kp + 1]);
            #pragma unroll
            for (int nt = 0; nt < 3; ++nt)
                mma16816(acc[nt], Al, bh[nt][kp], bh[nt][kp + 1]);
            #pragma unroll
            for (int nt = 0; nt < 3; ++nt)
                mma16816(acc[nt], Ah, bl[nt][kp], bl[nt][kp + 1]);
        }

        // ---- write k-partials ----
        {
            const int rr = lid >> 2, cc = (lid & 3) * 2;
            #pragma unroll
            for (int nt = 0; nt < 3; ++nt) {
                const int base = (ki * 24 + nt * 8 + cc) * 66 + mi * 16 + rr;
                red[base]          = acc[nt][0];
                red[base + 66]     = acc[nt][1];
                red[base + 8]      = acc[nt][2];
                red[base + 66 + 8] = acc[nt][3];
            }
        }
        __syncthreads();

        // ---- pointwise: each thread owns (col, bb) ----
        {
            float sr = br, sz = bz2, sn = bn2;
            #pragma unroll
            for (int kk = 0; kk < 4; ++kk) {
                sr += red[(kk * 24 + col) * 66 + bb];
                sz += red[(kk * 24 + 8 + col) * 66 + bb];
                sn += red[(kk * 24 + 16 + col) * 66 + bb];
            }
            const float r = 1.f / (1.f + expf(-(xr + sr)));
            const float z = 1.f / (1.f + expf(-(xz + sz)));
            const float n = tanhf(xn_ + r * sn);
            const float hnew = (1.f - z) * n + z * hprev;
            const float h = mk * hnew + (1.f - mk) * hprev;
            hprev = h;
            const size_t ob = (size_t)(d * 2 + nxt) * 2 * 32768;
            const __nv_bfloat16 hh = __float2bfloat16(h);
            g_h16t[ob + bb * 512 + c0 + col] = hh;
            g_h16t[ob + 32768 + bb * 512 + c0 + col] =
                __float2bfloat16(h - __bfloat162float(hh));
            hout[bb * 8 + col] = h;
        }
        __syncthreads();

        if (tid < 64) {
            float4* dst2 = (float4*)&out[((size_t)tid * 1024 + te) * 1024 + d * 512 + c0];
            dst2[0] = *(float4*)&hout[tid * 8];
            dst2[1] = *(float4*)&hout[tid * 8 + 4];
        }
        grid_bar();
    }
}

// ---------------------------------------------------------------------------
extern "C" void kernel_launch(void* const* d_in, const int* in_sizes, int n_in,
                              void* d_out, int out_size)
{
    const float* feats   = (const float*)d_in[0];
    const float* mask    = (const float*)d_in[1];
    const float* w_ih_lr = (const float*)d_in[2];
    const float* w_hh_lr = (const float*)d_in[3];
    const float* b_ih_lr = (const float*)d_in[4];
    const float* b_hh_lr = (const float*)d_in[5];
    const float* w_ih_rl = (const float*)d_in[6];
    const float* w_hh_rl = (const float*)d_in[7];
    const float* b_ih_rl = (const float*)d_in[8];
    const float* b_hh_rl = (const float*)d_in[9];
    float* out = (float*)d_out;

    cudaFuncSetAttribute(proj_mma, cudaFuncAttributeMaxDynamicSharedMemorySize, PROJ_SMEM);
    cudaFuncSetAttribute(gru_mma, cudaFuncAttributeMaxDynamicSharedMemorySize, GRU_SMEM);

    split_x_kernel<<<1024, 256>>>(feats);
    split_w_kernel<<<1536, 256>>>(w_ih_lr, w_ih_rl);
    proj_mma<<<dim3(12, 512, 2), 256, PROJ_SMEM>>>(b_ih_lr, b_ih_rl);
    gru_mma<<<dim3(64, 2), 512, GRU_SMEM>>>(mask, w_hh_lr, b_hh_lr,
                                            w_hh_rl, b_hh_rl, out);
}

// round 14
// speedup vs baseline: 2.3155x; 1.3585x over previous
#include <cuda_runtime.h>
#include <cuda_bf16.h>
#include <cstdint>
#include <math.h>

#define B_   64
#define L_   1024
#define IN_  512
#define H_   512
#define G3_  1536
#define NTOT 65536   // L_ * B_

// ---------------------------------------------------------------------------
// Device-global scratch (allocation APIs are forbidden)
// ---------------------------------------------------------------------------
__device__ float g_gx[(size_t)2 * G3_ * NTOT];        // [d][m][n=t*64+b]  805 MB
__device__ unsigned g_cnt2[2] = {0, 0};
__device__ unsigned g_gen2[2] = {0, 0};
__device__ __nv_bfloat16 g_xs[2][(size_t)L_ * B_ * IN_];      // [split][t*64+b][k]
__device__ __nv_bfloat16 g_ws[2][2][(size_t)G3_ * IN_];       // [d][split][m][k]
// h carry: [d][buf][split][b*512 + k]  bf16 hi/lo, double buffered
__device__ __align__(16) __nv_bfloat16 g_h16t[2 * 2 * 2 * 32768];

// ---------------------------------------------------------------------------
// Warp-level tensor-core helpers (base-arch legal: ldmatrix + mma.sync)
// ---------------------------------------------------------------------------
static __device__ __forceinline__ uint32_t smem_u32(const void* p) {
    uint32_t a;
    asm("{ .reg .u64 t; cvta.to.shared.u64 t, %1; cvt.u32.u64 %0, t; }" : "=r"(a) : "l"(p));
    return a;
}
static __device__ __forceinline__ void ldsm4(uint32_t* r, uint32_t addr) {
    asm volatile("ldmatrix.sync.aligned.m8n8.x4.shared.b16 {%0,%1,%2,%3}, [%4];"
                 : "=r"(r[0]), "=r"(r[1]), "=r"(r[2]), "=r"(r[3]) : "r"(addr));
}
static __device__ __forceinline__ void mma16816(float* c, const uint32_t* a,
                                                uint32_t b0, uint32_t b1) {
    asm volatile(
        "mma.sync.aligned.m16n8k16.row.col.f32.bf16.bf16.f32 "
        "{%0,%1,%2,%3}, {%4,%5,%6,%7}, {%8,%9}, {%0,%1,%2,%3};"
        : "+f"(c[0]), "+f"(c[1]), "+f"(c[2]), "+f"(c[3])
        : "r"(a[0]), "r"(a[1]), "r"(a[2]), "r"(a[3]), "r"(b0), "r"(b1));
}
#define CP_ASYNC16(dst, src) \
    asm volatile("cp.async.cg.shared.global [%0], [%1], 16;" :: "r"(dst), "l"(src))
#define CP_COMMIT asm volatile("cp.async.commit_group;" ::: "memory")
#define CP_WAIT0  asm volatile("cp.async.wait_group 0;" ::: "memory")
#define CP_WAIT1  asm volatile("cp.async.wait_group 1;" ::: "memory")

// ---------------------------------------------------------------------------
// Split kernels: fp32 -> bf16 hi/lo pairs
// ---------------------------------------------------------------------------
static __device__ __forceinline__ void split4(float4 v, __nv_bfloat162* ph,
                                              __nv_bfloat162* pl) {
    __nv_bfloat16 h0 = __float2bfloat16(v.x), h1 = __float2bfloat16(v.y);
    __nv_bfloat16 h2 = __float2bfloat16(v.z), h3 = __float2bfloat16(v.w);
    __nv_bfloat16 l0 = __float2bfloat16(v.x - __bfloat162float(h0));
    __nv_bfloat16 l1 = __float2bfloat16(v.y - __bfloat162float(h1));
    __nv_bfloat16 l2 = __float2bfloat16(v.z - __bfloat162float(h2));
    __nv_bfloat16 l3 = __float2bfloat16(v.w - __bfloat162float(h3));
    __nv_bfloat162 t;
    t.x = h0; t.y = h1; ph[0] = t;  t.x = h2; t.y = h3; ph[1] = t;
    t.x = l0; t.y = l1; pl[0] = t;  t.x = l2; t.y = l3; pl[1] = t;
}

__global__ __launch_bounds__(256) void split_x_kernel(const float* __restrict__ feats) {
    const int t = blockIdx.x;
    for (int i = threadIdx.x; i < 8192; i += 256) {
        const int b = i >> 7, q = i & 127;
        float4 v = ((const float4*)feats)[((size_t)b * 1024 + t) * 128 + q];
        const size_t base = ((size_t)t * 64 + b) * 512 + q * 4;
        split4(v, (__nv_bfloat162*)&g_xs[0][base], (__nv_bfloat162*)&g_xs[1][base]);
    }
}

__global__ __launch_bounds__(256) void split_w_kernel(const float* __restrict__ wlr,
                                                      const float* __restrict__ wrl) {
    const size_t n4 = (size_t)G3_ * IN_ / 4;
    for (size_t i = blockIdx.x * (size_t)blockDim.x + threadIdx.x; i < 2 * n4;
         i += (size_t)gridDim.x * blockDim.x) {
        const int d = i >= n4;
        const size_t j = d ? (i - n4) : i;
        float4 v = ((const float4*)(d ? wrl : wlr))[j];
        split4(v, (__nv_bfloat162*)&g_ws[d][0][j * 4], (__nv_bfloat162*)&g_ws[d][1][j * 4]);
    }
}

// ---------------------------------------------------------------------------
// HMMA projection (unchanged from round-13 passing version)
// ---------------------------------------------------------------------------
#define PROJ_SMEM 81920

__global__ __launch_bounds__(256) void proj_mma(const float* __restrict__ b_ih_lr,
                                                const float* __restrict__ b_ih_rl)
{
    extern __shared__ char smc[];
    const uint32_t sb = smem_u32(smc);
    const int tid = threadIdx.x, wid = tid >> 5, lid = tid & 31;
    const int wm = wid & 3, wn = wid >> 2;
    const int m0 = blockIdx.x * 128, n0 = blockIdx.y * 128, d = blockIdx.z;

    const __nv_bfloat16* wh = &g_ws[d][0][(size_t)m0 * 512];
    const __nv_bfloat16* wl = &g_ws[d][1][(size_t)m0 * 512];

    const int q  = tid & 3;
    const int ar = tid >> 2;
    const size_t aOff0 = (size_t)ar * 512 + q * 8;
    const size_t aOff1 = (size_t)(ar + 64) * 512 + q * 8;
    const int nA0 = n0 + ar, nA1 = n0 + ar + 64;
    const size_t bSrc0 = ((size_t)(d ? ((1023 - (nA0 >> 6)) * 64 + (nA0 & 63)) : nA0)) * 512 + q * 8;
    const size_t bSrc1 = ((size_t)(d ? ((1023 - (nA1 >> 6)) * 64 + (nA1 & 63)) : nA1)) * 512 + q * 8;
    const uint32_t sO0 = (uint32_t)(ar * 80 + q * 16);
    const uint32_t sO1 = (uint32_t)((ar + 64) * 80 + q * 16);

    const int mld = lid >> 3, lr8 = lid & 7;
    const uint32_t aBase = sb +
        (uint32_t)((wm * 32 + ((mld & 1) << 3) + lr8) * 80 + (((mld >> 1) << 3) << 1));
    const uint32_t bBase = sb + 20480u +
        (uint32_t)((wn * 64 + ((mld >> 1) << 3) + lr8) * 80 + (((mld & 1) << 3) << 1));

    float acc[2][8][4];
    #pragma unroll
    for (int f = 0; f < 2; ++f)
        #pragma unroll
        for (int nf = 0; nf < 8; ++nf)
            #pragma unroll
            for (int e = 0; e < 4; ++e) acc[f][nf][e] = 0.f;

    uint4 pAh0, pAh1, pAl0, pAl1, pBh0, pBh1, pBl0, pBl1;
    pAh0 = *(const uint4*)(wh + aOff0);  pAh1 = *(const uint4*)(wh + aOff1);
    pAl0 = *(const uint4*)(wl + aOff0);  pAl1 = *(const uint4*)(wl + aOff1);
    pBh0 = *(const uint4*)(&g_xs[0][bSrc0]);  pBh1 = *(const uint4*)(&g_xs[0][bSrc1]);
    pBl0 = *(const uint4*)(&g_xs[1][bSrc0]);  pBl1 = *(const uint4*)(&g_xs[1][bSrc1]);

    int s = 0;
    for (int kc = 0; kc < 512; kc += 32) {
        char* base = smc + s * 40960;
        *(uint4*)(base + sO0)          = pAh0;  *(uint4*)(base + sO1)          = pAh1;
        *(uint4*)(base + 10240 + sO0)  = pAl0;  *(uint4*)(base + 10240 + sO1)  = pAl1;
        *(uint4*)(base + 20480 + sO0)  = pBh0;  *(uint4*)(base + 20480 + sO1)  = pBh1;
        *(uint4*)(base + 30720 + sO0)  = pBl0;  *(uint4*)(base + 30720 + sO1)  = pBl1;
        __syncthreads();

        if (kc + 32 < 512) {
            const int kn = kc + 32;
            pAh0 = *(const uint4*)(wh + aOff0 + kn);  pAh1 = *(const uint4*)(wh + aOff1 + kn);
            pAl0 = *(const uint4*)(wl + aOff0 + kn);  pAl1 = *(const uint4*)(wl + aOff1 + kn);
            pBh0 = *(const uint4*)(&g_xs[0][bSrc0 + kn]);
            pBh1 = *(const uint4*)(&g_xs[0][bSrc1 + kn]);
            pBl0 = *(const uint4*)(&g_xs[1][bSrc0 + kn]);
            pBl1 = *(const uint4*)(&g_xs[1][bSrc1 + kn]);
        }

        const uint32_t so = (uint32_t)(s * 40960);
        #pragma unroll
        for (int j = 0; j < 2; ++j) {
            const uint32_t ko = so + j * 32;
            uint32_t Ah[2][4], Al[2][4], Bh[4][4], Bl[4][4];
            ldsm4(Ah[0], aBase + ko);
            ldsm4(Ah[1], aBase + ko + 1280);
            ldsm4(Al[0], aBase + ko + 10240);
            ldsm4(Al[1], aBase + ko + 10240 + 1280);
            #pragma unroll
            for (int p = 0; p < 4; ++p) {
                ldsm4(Bh[p], bBase + ko + p * 1280);
                ldsm4(Bl[p], bBase + ko + p * 1280 + 10240);
            }
            #pragma unroll
            for (int p = 0; p < 4; ++p)
                #pragma unroll
                for (int f = 0; f < 2; ++f) {
                    mma16816(acc[f][2 * p],     Ah[f], Bh[p][0], Bh[p][1]);
                    mma16816(acc[f][2 * p + 1], Ah[f], Bh[p][2], Bh[p][3]);
                }
            #pragma unroll
            for (int p = 0; p < 4; ++p)
                #pragma unroll
                for (int f = 0; f < 2; ++f) {
                    mma16816(acc[f][2 * p],     Al[f], Bh[p][0], Bh[p][1]);
                    mma16816(acc[f][2 * p + 1], Al[f], Bh[p][2], Bh[p][3]);
                }
            #pragma unroll
            for (int p = 0; p < 4; ++p)
                #pragma unroll
                for (int f = 0; f < 2; ++f) {
                    mma16816(acc[f][2 * p],     Ah[f], Bl[p][0], Bl[p][1]);
                    mma16816(acc[f][2 * p + 1], Ah[f], Bl[p][2], Bl[p][3]);
                }
        }
        s ^= 1;
    }

    const int r0 = lid >> 2, c2 = (lid & 3) * 2;
    const float* bias = d ? b_ih_rl : b_ih_lr;
    #pragma unroll
    for (int f = 0; f < 2; ++f) {
        const int mr = m0 + wm * 32 + f * 16 + r0;
        const float bz0 = bias[mr], bz1 = bias[mr + 8];
        float* row0 = &g_gx[((size_t)d * G3_ + mr) * NTOT];
        float* row1 = row0 + (size_t)8 * NTOT;
        #pragma unroll
        for (int nf = 0; nf < 8; ++nf) {
            const int nc = n0 + wn * 64 + nf * 8 + c2;
            float2 v0, v1;
            v0.x = acc[f][nf][0] + bz0;  v0.y = acc[f][nf][1] + bz0;
            v1.x = acc[f][nf][2] + bz1;  v1.y = acc[f][nf][3] + bz1;
            *(float2*)&row0[nc] = v0;
            *(float2*)&row1[nc] = v1;
        }
    }
}

// ---------------------------------------------------------------------------
// Per-direction grid barrier (64 blocks each; self-resetting, replay-safe)
// ---------------------------------------------------------------------------
__device__ __forceinline__ void grid_bar_dir(int d)
{
    __syncthreads();
    if (threadIdx.x == 0) {
        __threadfence();
        volatile unsigned* vgen = &g_gen2[d];
        const unsigned snap = *vgen;
        const unsigned old  = atomicAdd(&g_cnt2[d], 1);
        if (old == 63) {
            g_cnt2[d] = 0;
            __threadfence();
            atomicAdd(&g_gen2[d], 1);
        } else {
            while (*vgen == snap) { }
        }
        __threadfence();
    }
    __syncthreads();
}

// ---------------------------------------------------------------------------
// HMMA persistent recurrence, v2.
// Grid (32, 2, 2) = (col-slice of 16, batch-half of 32, dir). 512 thr.
// Warp (wid 0..15): mi = wid&1 (16 batch rows), ni = (wid>>1)&1 (n-half 24),
//                   ki = wid>>2 (k-slice 128; split 64+64 across two phases).
// smem (bytes):
//   hsH [32 b][1040]       0 .. 33280
//   hsL                33280 .. 66560
//   wsH [48 n][1040]   66560 .. 116480
//   wsL               116480 .. 166400
//   red [ki4][n48][66]166400 .. 217088
//   hout[32][16] f32  217088 .. 219136
// ---------------------------------------------------------------------------
#define GRU_SMEM 219136

__global__ void __launch_bounds__(512, 1) gru_mma(
    const float* __restrict__ mask,
    const float* __restrict__ w_hh_lr, const float* __restrict__ b_hh_lr,
    const float* __restrict__ w_hh_rl, const float* __restrict__ b_hh_rl,
    float* __restrict__ out)
{
    extern __shared__ char smc[];
    const uint32_t sb = smem_u32(smc);
    float* red  = (float*)(smc + 166400);
    float* hout = (float*)(smc + 217088);
    __nv_bfloat16* wsH16 = (__nv_bfloat16*)(smc + 66560);
    __nv_bfloat16* wsL16 = (__nv_bfloat16*)(smc + 116480);

    const int d     = blockIdx.z;
    const int bhalf = blockIdx.y;
    const int c0    = blockIdx.x * 16;
    const float* whh = d ? w_hh_rl : w_hh_lr;
    const float* bhh = d ? b_hh_rl : b_hh_lr;

    const int tid = threadIdx.x, wid = tid >> 5, lid = tid & 31;
    const int mi = wid & 1, ni = (wid >> 1) & 1, ki = wid >> 2;
    const int lr8 = lid & 7, mld = lid >> 3;
    const int col = wid, bb2 = lid;            // pointwise: (col 0..15, batch 0..31)
    const int bbg = bhalf * 32 + bb2;          // global batch of pointwise thread

    // ---- stage W (fp32 -> bf16 hi/lo) into smem: 48 rows = 3 gates x 16 cols ----
    for (int i = tid; i < 24576; i += 512) {
        const int n = i >> 9, k = i & 511;
        const float w = whh[((size_t)((n >> 4) * 512 + c0 + (n & 15))) * 512 + k];
        const __nv_bfloat16 hi = __float2bfloat16(w);
        wsH16[n * 520 + k] = hi;
        wsL16[n * 520 + k] = __float2bfloat16(w - __bfloat162float(hi));
    }
    // ---- zero h16 buffer 0 (this block's (col, b) slice) ----
    {
        const size_t base = (size_t)(d * 2 + 0) * 2 * 32768;
        g_h16t[base + (size_t)bbg * 512 + c0 + col]         = __float2bfloat16(0.f);
        g_h16t[base + 32768 + (size_t)bbg * 512 + c0 + col] = __float2bfloat16(0.f);
    }
    float hprev = 0.f;
    const float br  = bhh[c0 + col];
    const float bz2 = bhh[512 + c0 + col];
    const float bn2 = bhh[1024 + c0 + col];
    grid_bar_dir(d);

    // ---- ldsm bases ----
    const uint32_t aBaseH = sb + (uint32_t)((mi * 16 + (mld & 1) * 8 + lr8) * 1040
                                            + ki * 128 + (mld >> 1) * 16);
    const uint32_t aBaseL = aBaseH + 33280u;
    const uint32_t bBaseH = sb + 66560u + (uint32_t)((ni * 24 + lr8) * 1040
                                                     + ki * 128 + mld * 16);
    const uint32_t bBaseL = bBaseH + 49920u;

    // staging thread -> (row, chunk): idx 0..1023 per phase, 2 per thread
    const int rb0 = tid >> 5,      qq0 = tid & 31;        // idx = tid
    const int rb1 = (tid + 512) >> 5, qq1 = tid & 31;     // idx = tid + 512

    for (int t = 0; t < L_; ++t) {
        const int cur = t & 1, nxt = cur ^ 1;
        const size_t hb = (size_t)(d * 2 + cur) * 2 * 32768 + (size_t)bhalf * 32 * 512;

        // ---- phase-A loads (k 0..255), then phase-B loads (k 256..511) ----
        #pragma unroll
        for (int p = 0; p < 2; ++p) {
            const uint32_t dA = sb + (uint32_t)(rb0 * 1040 + p * 512 + qq0 * 16);
            const __nv_bfloat16* sA = &g_h16t[hb + rb0 * 512 + p * 256 + qq0 * 8];
            CP_ASYNC16(dA, sA);
            CP_ASYNC16(dA + 33280u, sA + 32768);
            const uint32_t dB = sb + (uint32_t)(rb1 * 1040 + p * 512 + qq1 * 16);
            const __nv_bfloat16* sB = &g_h16t[hb + rb1 * 512 + p * 256 + qq1 * 8];
            CP_ASYNC16(dB, sB);
            CP_ASYNC16(dB + 33280u, sB + 32768);
            CP_COMMIT;
        }

        // ---- independent global loads (overlap with cp.async) ----
        const int te = d ? (1023 - t) : t;
        const size_t gxn = (size_t)t * 64 + bbg;
        const float xr  = g_gx[((size_t)d * G3_ + c0 + col) * NTOT + gxn];
        const float xz  = g_gx[((size_t)d * G3_ + 512 + c0 + col) * NTOT + gxn];
        const float xn_ = g_gx[((size_t)d * G3_ + 1024 + c0 + col) * NTOT + gxn];
        const float mk  = mask[(size_t)bbg * 1024 + te];

        // ---- MMA: two phases (k 0..255 | 256..511), overlap load of B-half ----
        float acc[3][4];
        #pragma unroll
        for (int nt = 0; nt < 3; ++nt) {
            acc[nt][0] = 0.f; acc[nt][1] = 0.f; acc[nt][2] = 0.f; acc[nt][3] = 0.f;
        }
        #pragma unroll
        for (int p = 0; p < 2; ++p) {
            if (p == 0) { CP_WAIT1; } else { CP_WAIT0; }
            __syncthreads();
            const uint32_t pOff = (uint32_t)(p * 512);
            uint32_t bh[3][4], bl[3][4];
            #pragma unroll
            for (int kt = 0; kt < 4; ++kt) {
                if ((kt & 1) == 0) {
                    const uint32_t ko = pOff + (uint32_t)((kt >> 1) * 64);
                    #pragma unroll
                    for (int nt = 0; nt < 3; ++nt) {
                        ldsm4(bh[nt], bBaseH + nt * 8320u + ko);
                        ldsm4(bl[nt], bBaseL + nt * 8320u + ko);
                    }
                }
                uint32_t Ah[4], Al[4];
                ldsm4(Ah, aBaseH + pOff + kt * 32);
                ldsm4(Al, aBaseL + pOff + kt * 32);
                const int kp = (kt & 1) * 2;
                #pragma unroll
                for (int nt = 0; nt < 3; ++nt)
                    mma16816(acc[nt], Ah, bh[nt][kp], bh[nt][kp + 1]);
                #pragma unroll
                for (int nt = 0; nt < 3; ++nt)
                    mma16816(acc[nt], Al, bh[nt][kp], bh[nt][kp + 1]);
                #pragma unroll
                for (int nt = 0; nt < 3; ++nt)
                    mma16816(acc[nt], Ah, bl[nt][kp], bl[nt][kp + 1]);
            }
        }

        // ---- write k-partials: red[n (48)][m (66-pitch)] per ki ----
        {
            const int rr = lid >> 2, cc = (lid & 3) * 2;
            #pragma unroll
            for (int nt = 0; nt < 3; ++nt) {
                const int base = (ki * 48 + ni * 24 + nt * 8 + cc) * 66 + mi * 16 + rr;
                red[base]          = acc[nt][0];
                red[base + 66]     = acc[nt][1];
                red[base + 8]      = acc[nt][2];
                red[base + 66 + 8] = acc[nt][3];
            }
        }
        __syncthreads();

        // ---- pointwise: thread owns (col, bb2) ----
        {
            float sr = br, sz = bz2, sn = bn2;
            #pragma unroll
            for (int kk = 0; kk < 4; ++kk) {
                sr += red[(kk * 48 + col) * 66 + bb2];
                sz += red[(kk * 48 + 16 + col) * 66 + bb2];
                sn += red[(kk * 48 + 32 + col) * 66 + bb2];
            }
            const float r = 1.f / (1.f + expf(-(xr + sr)));
            const float z = 1.f / (1.f + expf(-(xz + sz)));
            const float n = tanhf(xn_ + r * sn);
            const float hnew = (1.f - z) * n + z * hprev;
            const float h = mk * hnew + (1.f - mk) * hprev;
            hprev = h;
            hout[bb2 * 16 + col] = h;
        }
        __syncthreads();

        // ---- coalesced bf16 hi/lo h-carry write (via hout transpose) ----
        {
            const int b = wid * 2 + (lid >> 4);    // 0..31
            const int cI = lid & 15;
            const float h = hout[b * 16 + cI];
            const __nv_bfloat16 hi = __float2bfloat16(h);
            const size_t ob = (size_t)(d * 2 + nxt) * 2 * 32768
                              + (size_t)(bhalf * 32 + b) * 512 + c0 + cI;
            g_h16t[ob]         = hi;
            g_h16t[ob + 32768] = __float2bfloat16(h - __bfloat162float(hi));
        }
        // ---- output write: 128 threads, float4 each ----
        if (tid < 128) {
            const int b = tid >> 2, qf = tid & 3;
            *(float4*)&out[((size_t)(bhalf * 32 + b) * 1024 + te) * 1024 + d * 512 + c0 + qf * 4]
                = *(float4*)&hout[b * 16 + qf * 4];
        }
        grid_bar_dir(d);
    }
}

// ---------------------------------------------------------------------------
extern "C" void kernel_launch(void* const* d_in, const int* in_sizes, int n_in,
                              void* d_out, int out_size)
{
    const float* feats   = (const float*)d_in[0];
    const float* mask    = (const float*)d_in[1];
    const float* w_ih_lr = (const float*)d_in[2];
    const float* w_hh_lr = (const float*)d_in[3];
    const float* b_ih_lr = (const float*)d_in[4];
    const float* b_hh_lr = (const float*)d_in[5];
    const float* w_ih_rl = (const float*)d_in[6];
    const float* w_hh_rl = (const float*)d_in[7];
    const float* b_ih_rl = (const float*)d_in[8];
    const float* b_hh_rl = (const float*)d_in[9];
    float* out = (float*)d_out;

    cudaFuncSetAttribute(proj_mma, cudaFuncAttributeMaxDynamicSharedMemorySize, PROJ_SMEM);
    cudaFuncSetAttribute(gru_mma, cudaFuncAttributeMaxDynamicSharedMemorySize, GRU_SMEM);

    split_x_kernel<<<1024, 256>>>(feats);
    split_w_kernel<<<1536, 256>>>(w_ih_lr, w_ih_rl);
    proj_mma<<<dim3(12, 512, 2), 256, PROJ_SMEM>>>(b_ih_lr, b_ih_rl);
    gru_mma<<<dim3(32, 2, 2), 512, GRU_SMEM>>>(mask, w_hh_lr, b_hh_lr,
                                               w_hh_rl, b_hh_rl, out);
}

// round 16
// speedup vs baseline: 2.4293x; 1.0491x over previous
#include <cuda_runtime.h>
#include <cuda_bf16.h>
#include <cstdint>
#include <math.h>

#define B_   64
#define L_   1024
#define IN_  512
#define H_   512
#define G3_  1536
#define NTOT 65536   // L_ * B_

// ---------------------------------------------------------------------------
// Device-global scratch (allocation APIs are forbidden)
// ---------------------------------------------------------------------------
__device__ float g_gx[(size_t)2 * G3_ * NTOT];        // [d][m][n=t*64+b]  805 MB
__device__ unsigned g_cnt4[4] = {0, 0, 0, 0};
__device__ unsigned g_gen4[4] = {0, 0, 0, 0};
__device__ __nv_bfloat16 g_xs[2][(size_t)L_ * B_ * IN_];      // [split][t*64+b][k]
__device__ __nv_bfloat16 g_ws[2][2][(size_t)G3_ * IN_];       // [d][split][m][k]
// h carry: [d][buf][split][b*512 + k]  bf16 hi/lo, double buffered
__device__ __align__(16) __nv_bfloat16 g_h16t[2 * 2 * 2 * 32768];

// ---------------------------------------------------------------------------
// Warp-level tensor-core helpers (base-arch legal: ldmatrix + mma.sync)
// ---------------------------------------------------------------------------
static __device__ __forceinline__ uint32_t smem_u32(const void* p) {
    uint32_t a;
    asm("{ .reg .u64 t; cvta.to.shared.u64 t, %1; cvt.u32.u64 %0, t; }" : "=r"(a) : "l"(p));
    return a;
}
static __device__ __forceinline__ void ldsm4(uint32_t* r, uint32_t addr) {
    asm volatile("ldmatrix.sync.aligned.m8n8.x4.shared.b16 {%0,%1,%2,%3}, [%4];"
                 : "=r"(r[0]), "=r"(r[1]), "=r"(r[2]), "=r"(r[3]) : "r"(addr));
}
static __device__ __forceinline__ void mma16816(float* c, const uint32_t* a,
                                                uint32_t b0, uint32_t b1) {
    asm volatile(
        "mma.sync.aligned.m16n8k16.row.col.f32.bf16.bf16.f32 "
        "{%0,%1,%2,%3}, {%4,%5,%6,%7}, {%8,%9}, {%0,%1,%2,%3};"
        : "+f"(c[0]), "+f"(c[1]), "+f"(c[2]), "+f"(c[3])
        : "r"(a[0]), "r"(a[1]), "r"(a[2]), "r"(a[3]), "r"(b0), "r"(b1));
}
#define CP_ASYNC16(dst, src) \
    asm volatile("cp.async.cg.shared.global [%0], [%1], 16;" :: "r"(dst), "l"(src))
#define CP_COMMIT asm volatile("cp.async.commit_group;" ::: "memory")
#define CP_WAIT0  asm volatile("cp.async.wait_group 0;" ::: "memory")
#define CP_WAIT1  asm volatile("cp.async.wait_group 1;" ::: "memory")

// ---------------------------------------------------------------------------
// Split kernels: fp32 -> bf16 hi/lo pairs
// ---------------------------------------------------------------------------
static __device__ __forceinline__ void split4(float4 v, __nv_bfloat162* ph,
                                              __nv_bfloat162* pl) {
    __nv_bfloat16 h0 = __float2bfloat16(v.x), h1 = __float2bfloat16(v.y);
    __nv_bfloat16 h2 = __float2bfloat16(v.z), h3 = __float2bfloat16(v.w);
    __nv_bfloat16 l0 = __float2bfloat16(v.x - __bfloat162float(h0));
    __nv_bfloat16 l1 = __float2bfloat16(v.y - __bfloat162float(h1));
    __nv_bfloat16 l2 = __float2bfloat16(v.z - __bfloat162float(h2));
    __nv_bfloat16 l3 = __float2bfloat16(v.w - __bfloat162float(h3));
    __nv_bfloat162 t;
    t.x = h0; t.y = h1; ph[0] = t;  t.x = h2; t.y = h3; ph[1] = t;
    t.x = l0; t.y = l1; pl[0] = t;  t.x = l2; t.y = l3; pl[1] = t;
}

__global__ __launch_bounds__(256) void split_x_kernel(const float* __restrict__ feats) {
    const int t = blockIdx.x;
    for (int i = threadIdx.x; i < 8192; i += 256) {
        const int b = i >> 7, q = i & 127;
        float4 v = ((const float4*)feats)[((size_t)b * 1024 + t) * 128 + q];
        const size_t base = ((size_t)t * 64 + b) * 512 + q * 4;
        split4(v, (__nv_bfloat162*)&g_xs[0][base], (__nv_bfloat162*)&g_xs[1][base]);
    }
}

__global__ __launch_bounds__(256) void split_w_kernel(const float* __restrict__ wlr,
                                                      const float* __restrict__ wrl) {
    const size_t n4 = (size_t)G3_ * IN_ / 4;
    for (size_t i = blockIdx.x * (size_t)blockDim.x + threadIdx.x; i < 2 * n4;
         i += (size_t)gridDim.x * blockDim.x) {
        const int d = i >= n4;
        const size_t j = d ? (i - n4) : i;
        float4 v = ((const float4*)(d ? wrl : wlr))[j];
        split4(v, (__nv_bfloat162*)&g_ws[d][0][j * 4], (__nv_bfloat162*)&g_ws[d][1][j * 4]);
    }
}

// ---------------------------------------------------------------------------
// HMMA projection (unchanged from round-14 passing version)
// ---------------------------------------------------------------------------
#define PROJ_SMEM 81920

__global__ __launch_bounds__(256) void proj_mma(const float* __restrict__ b_ih_lr,
                                                const float* __restrict__ b_ih_rl)
{
    extern __shared__ char smc[];
    const uint32_t sb = smem_u32(smc);
    const int tid = threadIdx.x, wid = tid >> 5, lid = tid & 31;
    const int wm = wid & 3, wn = wid >> 2;
    const int m0 = blockIdx.x * 128, n0 = blockIdx.y * 128, d = blockIdx.z;

    const __nv_bfloat16* wh = &g_ws[d][0][(size_t)m0 * 512];
    const __nv_bfloat16* wl = &g_ws[d][1][(size_t)m0 * 512];

    const int q  = tid & 3;
    const int ar = tid >> 2;
    const size_t aOff0 = (size_t)ar * 512 + q * 8;
    const size_t aOff1 = (size_t)(ar + 64) * 512 + q * 8;
    const int nA0 = n0 + ar, nA1 = n0 + ar + 64;
    const size_t bSrc0 = ((size_t)(d ? ((1023 - (nA0 >> 6)) * 64 + (nA0 & 63)) : nA0)) * 512 + q * 8;
    const size_t bSrc1 = ((size_t)(d ? ((1023 - (nA1 >> 6)) * 64 + (nA1 & 63)) : nA1)) * 512 + q * 8;
    const uint32_t sO0 = (uint32_t)(ar * 80 + q * 16);
    const uint32_t sO1 = (uint32_t)((ar + 64) * 80 + q * 16);

    const int mld = lid >> 3, lr8 = lid & 7;
    const uint32_t aBase = sb +
        (uint32_t)((wm * 32 + ((mld & 1) << 3) + lr8) * 80 + (((mld >> 1) << 3) << 1));
    const uint32_t bBase = sb + 20480u +
        (uint32_t)((wn * 64 + ((mld >> 1) << 3) + lr8) * 80 + (((mld & 1) << 3) << 1));

    float acc[2][8][4];
    #pragma unroll
    for (int f = 0; f < 2; ++f)
        #pragma unroll
        for (int nf = 0; nf < 8; ++nf)
            #pragma unroll
            for (int e = 0; e < 4; ++e) acc[f][nf][e] = 0.f;

    uint4 pAh0, pAh1, pAl0, pAl1, pBh0, pBh1, pBl0, pBl1;
    pAh0 = *(const uint4*)(wh + aOff0);  pAh1 = *(const uint4*)(wh + aOff1);
    pAl0 = *(const uint4*)(wl + aOff0);  pAl1 = *(const uint4*)(wl + aOff1);
    pBh0 = *(const uint4*)(&g_xs[0][bSrc0]);  pBh1 = *(const uint4*)(&g_xs[0][bSrc1]);
    pBl0 = *(const uint4*)(&g_xs[1][bSrc0]);  pBl1 = *(const uint4*)(&g_xs[1][bSrc1]);

    int s = 0;
    for (int kc = 0; kc < 512; kc += 32) {
        char* base = smc + s * 40960;
        *(uint4*)(base + sO0)          = pAh0;  *(uint4*)(base + sO1)          = pAh1;
        *(uint4*)(base + 10240 + sO0)  = pAl0;  *(uint4*)(base + 10240 + sO1)  = pAl1;
        *(uint4*)(base + 20480 + sO0)  = pBh0;  *(uint4*)(base + 20480 + sO1)  = pBh1;
        *(uint4*)(base + 30720 + sO0)  = pBl0;  *(uint4*)(base + 30720 + sO1)  = pBl1;
        __syncthreads();

        if (kc + 32 < 512) {
            const int kn = kc + 32;
            pAh0 = *(const uint4*)(wh + aOff0 + kn);  pAh1 = *(const uint4*)(wh + aOff1 + kn);
            pAl0 = *(const uint4*)(wl + aOff0 + kn);  pAl1 = *(const uint4*)(wl + aOff1 + kn);
            pBh0 = *(const uint4*)(&g_xs[0][bSrc0 + kn]);
            pBh1 = *(const uint4*)(&g_xs[0][bSrc1 + kn]);
            pBl0 = *(const uint4*)(&g_xs[1][bSrc0 + kn]);
            pBl1 = *(const uint4*)(&g_xs[1][bSrc1 + kn]);
        }

        const uint32_t so = (uint32_t)(s * 40960);
        #pragma unroll
        for (int j = 0; j < 2; ++j) {
            const uint32_t ko = so + j * 32;
            uint32_t Ah[2][4], Al[2][4], Bh[4][4], Bl[4][4];
            ldsm4(Ah[0], aBase + ko);
            ldsm4(Ah[1], aBase + ko + 1280);
            ldsm4(Al[0], aBase + ko + 10240);
            ldsm4(Al[1], aBase + ko + 10240 + 1280);
            #pragma unroll
            for (int p = 0; p < 4; ++p) {
                ldsm4(Bh[p], bBase + ko + p * 1280);
                ldsm4(Bl[p], bBase + ko + p * 1280 + 10240);
            }
            #pragma unroll
            for (int p = 0; p < 4; ++p)
                #pragma unroll
                for (int f = 0; f < 2; ++f) {
                    mma16816(acc[f][2 * p],     Ah[f], Bh[p][0], Bh[p][1]);
                    mma16816(acc[f][2 * p + 1], Ah[f], Bh[p][2], Bh[p][3]);
                }
            #pragma unroll
            for (int p = 0; p < 4; ++p)
                #pragma unroll
                for (int f = 0; f < 2; ++f) {
                    mma16816(acc[f][2 * p],     Al[f], Bh[p][0], Bh[p][1]);
                    mma16816(acc[f][2 * p + 1], Al[f], Bh[p][2], Bh[p][3]);
                }
            #pragma unroll
            for (int p = 0; p < 4; ++p)
                #pragma unroll
                for (int f = 0; f < 2; ++f) {
                    mma16816(acc[f][2 * p],     Ah[f], Bl[p][0], Bl[p][1]);
                    mma16816(acc[f][2 * p + 1], Ah[f], Bl[p][2], Bl[p][3]);
                }
        }
        s ^= 1;
    }

    const int r0 = lid >> 2, c2 = (lid & 3) * 2;
    const float* bias = d ? b_ih_rl : b_ih_lr;
    #pragma unroll
    for (int f = 0; f < 2; ++f) {
        const int mr = m0 + wm * 32 + f * 16 + r0;
        const float bz0 = bias[mr], bz1 = bias[mr + 8];
        float* row0 = &g_gx[((size_t)d * G3_ + mr) * NTOT];
        float* row1 = row0 + (size_t)8 * NTOT;
        #pragma unroll
        for (int nf = 0; nf < 8; ++nf) {
            const int nc = n0 + wn * 64 + nf * 8 + c2;
            float2 v0, v1;
            v0.x = acc[f][nf][0] + bz0;  v0.y = acc[f][nf][1] + bz0;
            v1.x = acc[f][nf][2] + bz1;  v1.y = acc[f][nf][3] + bz1;
            *(float2*)&row0[nc] = v0;
            *(float2*)&row1[nc] = v1;
        }
    }
}

// ---------------------------------------------------------------------------
// Group grid barrier: 32 blocks sharing (d, bhalf). Self-resetting, replay-safe.
// ---------------------------------------------------------------------------
__device__ __forceinline__ void grid_bar_grp(int grp)
{
    __syncthreads();
    if (threadIdx.x == 0) {
        __threadfence();
        volatile unsigned* vgen = &g_gen4[grp];
        const unsigned snap = *vgen;
        const unsigned old  = atomicAdd(&g_cnt4[grp], 1);
        if (old == 31) {
            g_cnt4[grp] = 0;
            __threadfence();
            atomicAdd(&g_gen4[grp], 1);
        } else {
            while (*vgen == snap) { }
        }
        __threadfence();
    }
    __syncthreads();
}

// ---------------------------------------------------------------------------
// HMMA persistent recurrence, v3.
// Grid (32, 2, 2) = (col-slice of 16, batch-half of 32, dir). 512 thr.
// Sync domain = the 32 blocks sharing (d, bhalf).
// Split accumulators (Ah*Bh | Al*Bh | Ah*Bl) break MMA RAW chains.
// smem layout unchanged from v2.
// ---------------------------------------------------------------------------
#define GRU_SMEM 219136

__global__ void __launch_bounds__(512, 1) gru_mma(
    const float* __restrict__ mask,
    const float* __restrict__ w_hh_lr, const float* __restrict__ b_hh_lr,
    const float* __restrict__ w_hh_rl, const float* __restrict__ b_hh_rl,
    float* __restrict__ out)
{
    extern __shared__ char smc[];
    const uint32_t sb = smem_u32(smc);
    float* red  = (float*)(smc + 166400);
    float* hout = (float*)(smc + 217088);
    __nv_bfloat16* wsH16 = (__nv_bfloat16*)(smc + 66560);
    __nv_bfloat16* wsL16 = (__nv_bfloat16*)(smc + 116480);

    const int d     = blockIdx.z;
    const int bhalf = blockIdx.y;
    const int grp   = d * 2 + bhalf;
    const int c0    = blockIdx.x * 16;
    const float* whh = d ? w_hh_rl : w_hh_lr;
    const float* bhh = d ? b_hh_rl : b_hh_lr;

    const int tid = threadIdx.x, wid = tid >> 5, lid = tid & 31;
    const int mi = wid & 1, ni = (wid >> 1) & 1, ki = wid >> 2;
    const int lr8 = lid & 7, mld = lid >> 3;
    const int col = wid, bb2 = lid;            // pointwise: (col 0..15, batch 0..31)
    const int bbg = bhalf * 32 + bb2;          // global batch of pointwise thread

    // ---- stage W (fp32 -> bf16 hi/lo) into smem: 48 rows = 3 gates x 16 cols ----
    for (int i = tid; i < 24576; i += 512) {
        const int n = i >> 9, k = i & 511;
        const float w = whh[((size_t)((n >> 4) * 512 + c0 + (n & 15))) * 512 + k];
        const __nv_bfloat16 hi = __float2bfloat16(w);
        wsH16[n * 520 + k] = hi;
        wsL16[n * 520 + k] = __float2bfloat16(w - __bfloat162float(hi));
    }
    // ---- zero h16 buffer 0 (this block's (col, b) slice) ----
    {
        const size_t base = (size_t)(d * 2 + 0) * 2 * 32768;
        g_h16t[base + (size_t)bbg * 512 + c0 + col]         = __float2bfloat16(0.f);
        g_h16t[base + 32768 + (size_t)bbg * 512 + c0 + col] = __float2bfloat16(0.f);
    }
    float hprev = 0.f;
    const float br  = bhh[c0 + col];
    const float bz2 = bhh[512 + c0 + col];
    const float bn2 = bhh[1024 + c0 + col];
    grid_bar_grp(grp);

    // ---- ldsm bases ----
    const uint32_t aBaseH = sb + (uint32_t)((mi * 16 + (mld & 1) * 8 + lr8) * 1040
                                            + ki * 128 + (mld >> 1) * 16);
    const uint32_t aBaseL = aBaseH + 33280u;
    const uint32_t bBaseH = sb + 66560u + (uint32_t)((ni * 24 + lr8) * 1040
                                                     + ki * 128 + mld * 16);
    const uint32_t bBaseL = bBaseH + 49920u;

    // staging thread -> (row, chunk): idx 0..1023 per phase, 2 per thread
    const int rb0 = tid >> 5,      qq0 = tid & 31;        // idx = tid
    const int rb1 = (tid + 512) >> 5, qq1 = tid & 31;     // idx = tid + 512

    for (int t = 0; t < L_; ++t) {
        const int cur = t & 1, nxt = cur ^ 1;
        const size_t hb = (size_t)(d * 2 + cur) * 2 * 32768 + (size_t)bhalf * 32 * 512;

        // ---- phase-A loads (k 0..255), then phase-B loads (k 256..511) ----
        #pragma unroll
        for (int p = 0; p < 2; ++p) {
            const uint32_t dA = sb + (uint32_t)(rb0 * 1040 + p * 512 + qq0 * 16);
            const __nv_bfloat16* sA = &g_h16t[hb + rb0 * 512 + p * 256 + qq0 * 8];
            CP_ASYNC16(dA, sA);
            CP_ASYNC16(dA + 33280u, sA + 32768);
            const uint32_t dB = sb + (uint32_t)(rb1 * 1040 + p * 512 + qq1 * 16);
            const __nv_bfloat16* sB = &g_h16t[hb + rb1 * 512 + p * 256 + qq1 * 8];
            CP_ASYNC16(dB, sB);
            CP_ASYNC16(dB + 33280u, sB + 32768);
            CP_COMMIT;
        }

        // ---- independent global loads (overlap with cp.async) ----
        const int te = d ? (1023 - t) : t;
        const size_t gxn = (size_t)t * 64 + bbg;
        const float xr  = g_gx[((size_t)d * G3_ + c0 + col) * NTOT + gxn];
        const float xz  = g_gx[((size_t)d * G3_ + 512 + c0 + col) * NTOT + gxn];
        const float xn_ = g_gx[((size_t)d * G3_ + 1024 + c0 + col) * NTOT + gxn];
        const float mk  = mask[(size_t)bbg * 1024 + te];

        // ---- MMA: two phases, 3 split accumulator sets (9 indep chains) ----
        float accA[3][4], accB[3][4], accC[3][4];
        #pragma unroll
        for (int nt = 0; nt < 3; ++nt)
            #pragma unroll
            for (int e = 0; e < 4; ++e) {
                accA[nt][e] = 0.f; accB[nt][e] = 0.f; accC[nt][e] = 0.f;
            }
        #pragma unroll
        for (int p = 0; p < 2; ++p) {
            if (p == 0) { CP_WAIT1; } else { CP_WAIT0; }
            __syncthreads();
            const uint32_t pOff = (uint32_t)(p * 512);
            uint32_t bh[3][4], bl[3][4];
            #pragma unroll
            for (int kt = 0; kt < 4; ++kt) {
                if ((kt & 1) == 0) {
                    const uint32_t ko = pOff + (uint32_t)((kt >> 1) * 64);
                    #pragma unroll
                    for (int nt = 0; nt < 3; ++nt) {
                        ldsm4(bh[nt], bBaseH + nt * 8320u + ko);
                        ldsm4(bl[nt], bBaseL + nt * 8320u + ko);
                    }
                }
                uint32_t Ah[4], Al[4];
                ldsm4(Ah, aBaseH + pOff + kt * 32);
                ldsm4(Al, aBaseL + pOff + kt * 32);
                const int kp = (kt & 1) * 2;
                #pragma unroll
                for (int nt = 0; nt < 3; ++nt)
                    mma16816(accA[nt], Ah, bh[nt][kp], bh[nt][kp + 1]);
                #pragma unroll
                for (int nt = 0; nt < 3; ++nt)
                    mma16816(accB[nt], Al, bh[nt][kp], bh[nt][kp + 1]);
                #pragma unroll
                for (int nt = 0; nt < 3; ++nt)
                    mma16816(accC[nt], Ah, bl[nt][kp], bl[nt][kp + 1]);
            }
        }

        // ---- write k-partials: red[n (48)][m (66-pitch)] per ki ----
        {
            const int rr = lid >> 2, cc = (lid & 3) * 2;
            #pragma unroll
            for (int nt = 0; nt < 3; ++nt) {
                const int base = (ki * 48 + ni * 24 + nt * 8 + cc) * 66 + mi * 16 + rr;
                red[base]          = accA[nt][0] + accB[nt][0] + accC[nt][0];
                red[base + 66]     = accA[nt][1] + accB[nt][1] + accC[nt][1];
                red[base + 8]      = accA[nt][2] + accB[nt][2] + accC[nt][2];
                red[base + 66 + 8] = accA[nt][3] + accB[nt][3] + accC[nt][3];
            }
        }
        __syncthreads();

        // ---- pointwise: thread owns (col, bb2) ----
        {
            float sr = br, sz = bz2, sn = bn2;
            #pragma unroll
            for (int kk = 0; kk < 4; ++kk) {
                sr += red[(kk * 48 + col) * 66 + bb2];
                sz += red[(kk * 48 + 16 + col) * 66 + bb2];
                sn += red[(kk * 48 + 32 + col) * 66 + bb2];
            }
            const float er = __expf(-(xr + sr));
            const float r  = __fdividef(1.f, 1.f + er);
            const float ez = __expf(-(xz + sz));
            const float z  = __fdividef(1.f, 1.f + ez);
            const float ta = xn_ + r * sn;
            const float e2 = __expf(-2.f * ta);
            const float n  = __fdividef(2.f, 1.f + e2) - 1.f;   // tanh(ta)
            const float hnew = (1.f - z) * n + z * hprev;
            const float h = mk * hnew + (1.f - mk) * hprev;
            hprev = h;
            hout[bb2 * 16 + col] = h;
        }
        __syncthreads();

        // ---- coalesced bf16 hi/lo h-carry write (via hout transpose) ----
        {
            const int b = wid * 2 + (lid >> 4);    // 0..31
            const int cI = lid & 15;
            const float h = hout[b * 16 + cI];
            const __nv_bfloat16 hi = __float2bfloat16(h);
            const size_t ob = (size_t)(d * 2 + nxt) * 2 * 32768
                              + (size_t)(bhalf * 32 + b) * 512 + c0 + cI;
            g_h16t[ob]         = hi;
            g_h16t[ob + 32768] = __float2bfloat16(h - __bfloat162float(hi));
        }
        // ---- output write: 128 threads, float4 each ----
        if (tid < 128) {
            const int b = tid >> 2, qf = tid & 3;
            *(float4*)&out[((size_t)(bhalf * 32 + b) * 1024 + te) * 1024 + d * 512 + c0 + qf * 4]
                = *(float4*)&hout[b * 16 + qf * 4];
        }
        grid_bar_grp(grp);
    }
}

// ---------------------------------------------------------------------------
extern "C" void kernel_launch(void* const* d_in, const int* in_sizes, int n_in,
                              void* d_out, int out_size)
{
    const float* feats   = (const float*)d_in[0];
    const float* mask    = (const float*)d_in[1];
    const float* w_ih_lr = (const float*)d_in[2];
    const float* w_hh_lr = (const float*)d_in[3];
    const float* b_ih_lr = (const float*)d_in[4];
    const float* b_hh_lr = (const float*)d_in[5];
    const float* w_ih_rl = (const float*)d_in[6];
    const float* w_hh_rl = (const float*)d_in[7];
    const float* b_ih_rl = (const float*)d_in[8];
    const float* b_hh_rl = (const float*)d_in[9];
    float* out = (float*)d_out;

    cudaFuncSetAttribute(proj_mma, cudaFuncAttributeMaxDynamicSharedMemorySize, PROJ_SMEM);
    cudaFuncSetAttribute(gru_mma, cudaFuncAttributeMaxDynamicSharedMemorySize, GRU_SMEM);

    split_x_kernel<<<1024, 256>>>(feats);
    split_w_kernel<<<1536, 256>>>(w_ih_lr, w_ih_rl);
    proj_mma<<<dim3(12, 512, 2), 256, PROJ_SMEM>>>(b_ih_lr, b_ih_rl);
    gru_mma<<<dim3(32, 2, 2), 512, GRU_SMEM>>>(mask, w_hh_lr, b_hh_lr,
                                               w_hh_rl, b_hh_rl, out);
}